// round 1
// baseline (speedup 1.0000x reference)
#include <cuda_runtime.h>
#include <math.h>

// ---------------------------------------------------------------------------
// ProjectionDecoder: Wigner rotate -> S2 ifft -> grid_sample -> convtranspose
// angles (2048,3) f32; spectrum (49,10,2) f32; wt (10,1,4,4) f32; bt (1) f32
// out (2048,1,128,128) f32
// ---------------------------------------------------------------------------

#define NPOSE 2048
#define MTOT  49
#define NREP  10
#define NJK   196     // 14*14
#define NPTS  4096    // 64*64
#define NSLOT 4753    // sum (2l+1)^3, l=0..6

__device__ float       g_tcoef[NSLOT];
__device__ signed char g_tpc[NSLOT];
__device__ signed char g_tps[NSLOT];
__device__ float       g_Yre[MTOT * NJK];
__device__ float       g_Yim[MTOT * NJK];
__device__ int         g_gx0[NPTS];
__device__ int         g_gy0[NPTS];
__device__ float       g_gwx[NPTS];
__device__ float       g_gwy[NPTS];

__device__ __forceinline__ double dfact(int n) {
    double f = 1.0;
    for (int i = 2; i <= n; i++) f *= (double)i;
    return f;
}

// slotbase[l] = sum_{k<l} (2k+1)^3 = l^2 (2 l^2 - 1)
__device__ __forceinline__ int slotbase(int l) { return l * l * (2 * l * l - 1); }
// dloff[l] = sum_{k<l} (2k+1)^2 = l(4l^2-1)/3
__device__ __forceinline__ int dloff(int l) { return l * (4 * l * l - 1) / 3; }

static constexpr double PI_D = 3.141592653589793238462643383279502884;

// ---------------------------------------------------------------------------
// Setup kernel: input-independent tables (runs each launch; deterministic)
// ---------------------------------------------------------------------------
__global__ void setup_kernel() {
    int g = blockIdx.x * blockDim.x + threadIdx.x;

    if (g < NSLOT) {
        // Wigner term slot tables: slot -> (l, i=mp+l, j=m+l, k)
        int l = (g >= 1) + (g >= 28) + (g >= 153) + (g >= 496) + (g >= 1225) + (g >= 2556);
        int n1 = 2 * l + 1;
        int rem = g - slotbase(l);
        int i = rem / (n1 * n1);
        int j = (rem / n1) % n1;
        int k = rem % n1;
        int mp = i - l, m = j - l;
        int kmin = max(0, m - mp);
        int kmax = min(l + m, l - mp);
        float coef = 0.0f;
        int pc = 0, ps = 0;
        if (k >= kmin && k <= kmax) {
            double pref = sqrt(dfact(l + mp) * dfact(l - mp) * dfact(l + m) * dfact(l - m));
            double c = pref / (dfact(l + m - k) * dfact(k) * dfact(l - mp - k) * dfact(mp - m + k));
            if ((mp - m + k) & 1) c = -c;
            coef = (float)c;
            pc = 2 * l + m - mp - 2 * k;
            ps = mp - m + 2 * k;
        }
        g_tcoef[g] = coef;
        g_tpc[g] = (signed char)pc;
        g_tps[g] = (signed char)ps;
    } else if (g >= 5120 && g < 5120 + NJK) {
        // Spherical harmonic table Y (49, 14, 14)
        int jk = g - 5120;
        int j = jk / 14, k = jk % 14;
        double beta = PI_D * (2.0 * j + 1.0) / 28.0;   // 4B = 28
        double x = cos(beta), sx = sin(beta);
        double P[7][7];
        for (int a = 0; a < 7; a++)
            for (int b = 0; b < 7; b++) P[a][b] = 0.0;
        P[0][0] = 1.0;
        for (int m = 1; m <= 6; m++) P[m][m] = -(2.0 * m - 1.0) * sx * P[m - 1][m - 1];
        for (int m = 0; m <= 6; m++) {
            if (m + 1 <= 6) P[m + 1][m] = (2.0 * m + 1.0) * x * P[m][m];
            for (int l = m + 2; l <= 6; l++)
                P[l][m] = ((2.0 * l - 1.0) * x * P[l - 1][m] - (l + m - 1.0) * P[l - 2][m]) / (double)(l - m);
        }
        double alk = 2.0 * PI_D * (double)k / 14.0;
        for (int l = 0; l <= 6; l++) {
            for (int m = 0; m <= l; m++) {
                double Nn = sqrt((2.0 * l + 1.0) / (4.0 * PI_D) * dfact(l - m) / dfact(l + m));
                double pr = Nn * P[l][m];
                double yre = pr * cos(m * alk);
                double yim = pr * sin(m * alk);
                g_Yre[(l * l + l + m) * NJK + jk] = (float)yre;
                g_Yim[(l * l + l + m) * NJK + jk] = (float)yim;
                if (m > 0) {
                    double sgn = (m & 1) ? -1.0 : 1.0;
                    g_Yre[(l * l + l - m) * NJK + jk] = (float)(sgn * yre);
                    g_Yim[(l * l + l - m) * NJK + jk] = (float)(-sgn * yim);
                }
            }
        }
    } else if (g >= 8192 && g < 8192 + NPTS) {
        // Orthographic grid -> bilinear tap table (H = W = 14, align_corners=False)
        int p = g - 8192;
        int iy = p / 64, ix = p % 64;
        double step = 1.6 / 63.0;
        double yv = -0.8 + iy * step;
        double xv = -0.8 + ix * step;
        double rho = sqrt(xv * xv + yv * yv);
        double th = asin(rho > 1.0 ? 1.0 : rho);
        double ph = atan2(yv, xv);
        float gx = (float)(ph / PI_D);
        float gy = (float)(2.0 * th / PI_D - 1.0);
        float gpx = (gx + 1.0f) * 7.0f - 0.5f;
        float gpy = (gy + 1.0f) * 7.0f - 0.5f;
        float x0 = floorf(gpx), y0 = floorf(gpy);
        g_gx0[p] = (int)x0;
        g_gy0[p] = (int)y0;
        g_gwx[p] = gpx - x0;
        g_gwy[p] = gpy - y0;
    }
}

// ---------------------------------------------------------------------------
// Main fused kernel: one block per pose n
// ---------------------------------------------------------------------------
// shared layout (floats):
//   dS    [0,455)      wigner d matrices (l-major)
//   cpow  [455,468)    cos(beta/2)^e
//   spow  [468,481)    sin(beta/2)^e
//   cA/sA [481,495)    cos/sin(m*alpha), m=0..6
//   cG/sG [495,509)    cos/sin(m*gamma)
//   SreS  [512,1002)   rotated spectrum re (49 x 10)
//   SimS  [1002,1492)
//   sigS  [1536,3496)  signal (10 x 196)
//   wS    [3500,3660)  deconv weights (10 x 16)
//   projS [3664,44624) projection (10 x 4096)
#define SMEM_FLOATS 44624
#define SMEM_BYTES  (SMEM_FLOATS * 4)

__global__ void __launch_bounds__(256)
decoder_kernel(const float* __restrict__ angles,
               const float* __restrict__ spectrum,
               const float* __restrict__ wt,
               const float* __restrict__ bt,
               float* __restrict__ out) {
    extern __shared__ float sm[];
    float* dS   = sm;
    float* cpow = sm + 455;
    float* spow = sm + 468;
    float* cA   = sm + 481;
    float* sA   = sm + 488;
    float* cG   = sm + 495;
    float* sG   = sm + 502;
    float* SreS = sm + 512;
    float* SimS = sm + 1002;
    float* sigS = sm + 1536;
    float* wS   = sm + 3500;
    float* projS = sm + 3664;

    const int n = blockIdx.x;
    const int tid = threadIdx.x;

    const float alpha = angles[3 * n + 0];
    const float beta  = angles[3 * n + 1];
    const float gamma = angles[3 * n + 2];
    const float bias = bt[0];

    // --- Phase A0: trig tables & weights ---
    if (tid < 7) {
        float s, c;
        sincosf((float)tid * alpha, &s, &c);
        cA[tid] = c; sA[tid] = s;
    } else if (tid < 14) {
        int m = tid - 7;
        float s, c;
        sincosf((float)m * gamma, &s, &c);
        cG[m] = c; sG[m] = s;
    } else if (tid == 14) {
        float sb, cb;
        sincosf(0.5f * beta, &sb, &cb);
        float cp = 1.0f, spw = 1.0f;
        for (int e = 0; e < 13; e++) {
            cpow[e] = cp; spow[e] = spw;
            cp *= cb; spw *= sb;
        }
    }
    if (tid < 160) wS[tid] = wt[tid];
    __syncthreads();

    // --- Phase A1: Wigner small-d matrices, one thread per (l,i,j) ---
    for (int t = tid; t < 455; t += 256) {
        int l = (t >= 1) + (t >= 10) + (t >= 35) + (t >= 84) + (t >= 165) + (t >= 286);
        int n1 = 2 * l + 1;
        int loc = t - dloff(l);
        int base = slotbase(l) + loc * n1;
        float sum = 0.0f;
        for (int k = 0; k < n1; k++) {
            float cf = g_tcoef[base + k];
            int pc = (int)g_tpc[base + k];
            int ps = (int)g_tps[base + k];
            sum += cf * cpow[pc] * spow[ps];
        }
        dS[t] = sum;
    }
    __syncthreads();

    // --- Phase A2: complex Wigner-D rotate; one thread per output row ---
    for (int row = tid; row < MTOT; row += 256) {
        int l = (row >= 1) + (row >= 4) + (row >= 9) + (row >= 16) + (row >= 25) + (row >= 36);
        int i = row - l * l;
        int mp = i - l;
        int n1 = 2 * l + 1;
        float camp = cA[mp < 0 ? -mp : mp];
        float samp = mp < 0 ? -sA[-mp] : sA[mp];
        float are[NREP], aim[NREP];
#pragma unroll
        for (int r = 0; r < NREP; r++) { are[r] = 0.0f; aim[r] = 0.0f; }
        const float* drow = dS + dloff(l) + i * n1;
        for (int j = 0; j < n1; j++) {
            int m = j - l;
            float cg = cG[m < 0 ? -m : m];
            float sg = m < 0 ? -sG[-m] : sG[m];
            float cosang = camp * cg - samp * sg;
            float sinang = samp * cg + camp * sg;
            float dd = drow[j];
            float Dre = dd * cosang;
            float Dim = -dd * sinang;
            const float* sp2 = spectrum + (l * l + j) * 2 * NREP;
#pragma unroll
            for (int r = 0; r < NREP; r++) {
                float sre = sp2[2 * r];
                float sim = sp2[2 * r + 1];
                are[r] += Dre * sre - Dim * sim;
                aim[r] += Dre * sim + Dim * sre;
            }
        }
#pragma unroll
        for (int r = 0; r < NREP; r++) {
            SreS[row * NREP + r] = are[r];
            SimS[row * NREP + r] = aim[r];
        }
    }
    __syncthreads();

    // --- Phase B: S2 inverse transform; one thread per (j,k) grid point ---
    for (int jk = tid; jk < NJK; jk += 256) {
        float acc[NREP];
#pragma unroll
        for (int r = 0; r < NREP; r++) acc[r] = 0.0f;
        for (int m = 0; m < MTOT; m++) {
            float yre = g_Yre[m * NJK + jk];
            float yim = g_Yim[m * NJK + jk];
#pragma unroll
            for (int r = 0; r < NREP; r++)
                acc[r] += SreS[m * NREP + r] * yre - SimS[m * NREP + r] * yim;
        }
#pragma unroll
        for (int r = 0; r < NREP; r++) sigS[r * NJK + jk] = acc[r];
    }
    __syncthreads();

    // --- Phase C: bilinear grid sample (zero padding) ---
    for (int p = tid; p < NPTS; p += 256) {
        int x0 = g_gx0[p], y0 = g_gy0[p];
        float fx = g_gwx[p], fy = g_gwy[p];
        int x1 = x0 + 1, y1 = y0 + 1;
        float vx0 = (x0 >= 0 && x0 < 14) ? 1.0f : 0.0f;
        float vx1 = (x1 >= 0 && x1 < 14) ? 1.0f : 0.0f;
        float vy0 = (y0 >= 0 && y0 < 14) ? 1.0f : 0.0f;
        float vy1 = (y1 >= 0 && y1 < 14) ? 1.0f : 0.0f;
        float w00 = (1.0f - fx) * (1.0f - fy) * vx0 * vy0;
        float w01 = fx * (1.0f - fy) * vx1 * vy0;
        float w10 = (1.0f - fx) * fy * vx0 * vy1;
        float w11 = fx * fy * vx1 * vy1;
        int xc0 = min(max(x0, 0), 13), xc1 = min(max(x1, 0), 13);
        int yc0 = min(max(y0, 0), 13), yc1 = min(max(y1, 0), 13);
        int i00 = yc0 * 14 + xc0, i01 = yc0 * 14 + xc1;
        int i10 = yc1 * 14 + xc0, i11 = yc1 * 14 + xc1;
#pragma unroll
        for (int r = 0; r < NREP; r++) {
            const float* s = sigS + r * NJK;
            projS[r * NPTS + p] = w00 * s[i00] + w01 * s[i01] + w10 * s[i10] + w11 * s[i11];
        }
    }
    __syncthreads();

    // --- Phase D: ConvTranspose2d(10->1, k=4, s=2, p=1); 8x4 output tile/thread ---
    float* outn = out + (size_t)n * 16384;
    for (int t = tid; t < 512; t += 256) {
        int ty = t >> 5;        // 0..15 (8 output rows each)
        int tx = t & 31;        // 0..31 (4 output cols each)
        int p0 = 4 * ty;        // proj row of first output quad
        int q0 = 2 * tx;        // proj col of first output quad
        float acc[8][4];
#pragma unroll
        for (int dy = 0; dy < 8; dy++)
#pragma unroll
            for (int dx = 0; dx < 4; dx++) acc[dy][dx] = bias;

#pragma unroll
        for (int c = 0; c < NREP; c++) {
            float w[16];
#pragma unroll
            for (int kk = 0; kk < 16; kk++) w[kk] = wS[c * 16 + kk];
            float P[6][4];
#pragma unroll
            for (int yy = 0; yy < 6; yy++) {
                int iy = p0 - 1 + yy;
                bool vy = ((unsigned)iy < 64u);
                int iyc = vy ? iy : 0;
#pragma unroll
                for (int xx = 0; xx < 4; xx++) {
                    int ixx = q0 - 1 + xx;
                    bool v = vy && ((unsigned)ixx < 64u);
                    int ixc = v ? ixx : 0;
                    float val = projS[c * NPTS + iyc * 64 + ixc];
                    P[yy][xx] = v ? val : 0.0f;
                }
            }
#pragma unroll
            for (int dy = 0; dy < 8; dy++) {
                int pl = dy >> 1;
                int py = dy & 1;
                int ry0 = py ? pl + 2 : pl + 1;
                int ry1 = py ? pl + 1 : pl;
                int kya = py ? 0 : 1;
                int kyb = py ? 2 : 3;
#pragma unroll
                for (int dx = 0; dx < 4; dx++) {
                    int ql = dx >> 1;
                    int px = dx & 1;
                    int rx0 = px ? ql + 2 : ql + 1;
                    int rx1 = px ? ql + 1 : ql;
                    int kxa = px ? 0 : 1;
                    int kxb = px ? 2 : 3;
                    acc[dy][dx] += P[ry0][rx0] * w[kya * 4 + kxa]
                                 + P[ry0][rx1] * w[kya * 4 + kxb]
                                 + P[ry1][rx0] * w[kyb * 4 + kxa]
                                 + P[ry1][rx1] * w[kyb * 4 + kxb];
                }
            }
        }
#pragma unroll
        for (int dy = 0; dy < 8; dy++) {
            float4 v = make_float4(acc[dy][0], acc[dy][1], acc[dy][2], acc[dy][3]);
            *reinterpret_cast<float4*>(outn + (size_t)(8 * ty + dy) * 128 + 4 * tx) = v;
        }
    }
}

// ---------------------------------------------------------------------------
extern "C" void kernel_launch(void* const* d_in, const int* in_sizes, int n_in,
                              void* d_out, int out_size) {
    const float* angles   = (const float*)d_in[0];
    const float* spectrum = (const float*)d_in[1];
    const float* wt       = (const float*)d_in[2];
    const float* bt       = (const float*)d_in[3];
    float* out = (float*)d_out;

    cudaFuncSetAttribute(decoder_kernel,
                         cudaFuncAttributeMaxDynamicSharedMemorySize, SMEM_BYTES);

    setup_kernel<<<12, 1024>>>();
    decoder_kernel<<<NPOSE, 256, SMEM_BYTES>>>(angles, spectrum, wt, bt, out);
}

// round 5
// speedup vs baseline: 1.2006x; 1.2006x over previous
#include <cuda_runtime.h>
#include <math.h>

// ---------------------------------------------------------------------------
// ProjectionDecoder: Wigner rotate -> S2 ifft -> grid_sample -> convtranspose
// angles (2048,3) f32; spectrum (49,10,2) f32; wt (10,1,4,4) f32; bt (1) f32
// out (2048,1,128,128) f32
// ---------------------------------------------------------------------------

#define NPOSE 2048
#define MTOT  49
#define NREP  10
#define NJK   196     // 14*14
#define NPTS  4096    // 64*64
#define NSLOT 4753    // sum (2l+1)^3, l=0..6
#define BLOCK 384

__device__ float       g_tcoef[NSLOT];
__device__ signed char g_tpc[NSLOT];
__device__ signed char g_tps[NSLOT];
__device__ float2      g_Yc[MTOT * NJK];   // {Yre, Yim}
__device__ float4      g_tw[NPTS];         // bilinear weights (validity folded)
__device__ int4        g_ti[NPTS];         // clamped gather indices into 14x14

__device__ __forceinline__ double dfact(int n) {
    double f = 1.0;
    for (int i = 2; i <= n; i++) f *= (double)i;
    return f;
}

// slotbase[l] = sum_{k<l} (2k+1)^3 = l^2 (2 l^2 - 1)
__device__ __forceinline__ int slotbase(int l) { return l * l * (2 * l * l - 1); }
// dloff[l] = sum_{k<l} (2k+1)^2 = l(4l^2-1)/3
__device__ __forceinline__ int dloff(int l) { return l * (4 * l * l - 1) / 3; }

#define PI_F 3.14159265358979323846f

// ---------------------------------------------------------------------------
// Setup kernel: input-independent tables. fp32 transcendentals,
// doubles only for exact factorial products. 256 threads/block (reg-safe).
// ---------------------------------------------------------------------------
__global__ void setup_kernel() {
    int g = blockIdx.x * blockDim.x + threadIdx.x;

    if (g < NSLOT) {
        // Wigner term slot tables: slot -> (l, i=mp+l, j=m+l, k)
        int l = (g >= 1) + (g >= 28) + (g >= 153) + (g >= 496) + (g >= 1225) + (g >= 2556);
        int n1 = 2 * l + 1;
        int rem = g - slotbase(l);
        int i = rem / (n1 * n1);
        int j = (rem / n1) % n1;
        int k = rem % n1;
        int mp = i - l, m = j - l;
        int kmin = max(0, m - mp);
        int kmax = min(l + m, l - mp);
        float coef = 0.0f;
        int pc = 0, ps = 0;
        if (k >= kmin && k <= kmax) {
            double pref = sqrt(dfact(l + mp) * dfact(l - mp) * dfact(l + m) * dfact(l - m));
            double c = pref / (dfact(l + m - k) * dfact(k) * dfact(l - mp - k) * dfact(mp - m + k));
            if ((mp - m + k) & 1) c = -c;
            coef = (float)c;
            pc = 2 * l + m - mp - 2 * k;
            ps = mp - m + 2 * k;
        }
        g_tcoef[g] = coef;
        g_tpc[g] = (signed char)pc;
        g_tps[g] = (signed char)ps;
    } else if (g >= 5120 && g < 5120 + NJK) {
        // Spherical harmonic table Y (49, 14, 14) -- fp32
        int jk = g - 5120;
        int j = jk / 14, k = jk % 14;
        float beta = PI_F * (2.0f * j + 1.0f) / 28.0f;   // 4B = 28
        float x, sx;
        sincosf(beta, &sx, &x);
        float P[7][7];
#pragma unroll
        for (int a = 0; a < 7; a++)
#pragma unroll
            for (int b = 0; b < 7; b++) P[a][b] = 0.0f;
        P[0][0] = 1.0f;
        for (int m = 1; m <= 6; m++) P[m][m] = -(2.0f * m - 1.0f) * sx * P[m - 1][m - 1];
        for (int m = 0; m <= 6; m++) {
            if (m + 1 <= 6) P[m + 1][m] = (2.0f * m + 1.0f) * x * P[m][m];
            for (int l = m + 2; l <= 6; l++)
                P[l][m] = ((2.0f * l - 1.0f) * x * P[l - 1][m] - (l + m - 1.0f) * P[l - 2][m]) / (float)(l - m);
        }
        float alk = 2.0f * PI_F * (float)k / 14.0f;
        for (int l = 0; l <= 6; l++) {
            for (int m = 0; m <= l; m++) {
                float Nn = sqrtf((2.0f * l + 1.0f) / (4.0f * PI_F)
                                 * (float)(dfact(l - m) / dfact(l + m)));
                float pr = Nn * P[l][m];
                float sm_, cm_;
                sincosf((float)m * alk, &sm_, &cm_);
                float yre = pr * cm_;
                float yim = pr * sm_;
                g_Yc[(l * l + l + m) * NJK + jk] = make_float2(yre, yim);
                if (m > 0) {
                    float sgn = (m & 1) ? -1.0f : 1.0f;
                    g_Yc[(l * l + l - m) * NJK + jk] = make_float2(sgn * yre, -sgn * yim);
                }
            }
        }
    } else if (g >= 8192 && g < 8192 + NPTS) {
        // Orthographic grid -> packed bilinear taps (H = W = 14, a_c=False)
        int p = g - 8192;
        int iy = p / 64, ix = p % 64;
        float step = 1.6f / 63.0f;
        float yv = -0.8f + iy * step;
        float xv = -0.8f + ix * step;
        float rho = sqrtf(xv * xv + yv * yv);
        float th = asinf(fminf(rho, 1.0f));
        float ph = atan2f(yv, xv);
        float gx = ph / PI_F;
        float gy = 2.0f * th / PI_F - 1.0f;
        float gpx = (gx + 1.0f) * 7.0f - 0.5f;
        float gpy = (gy + 1.0f) * 7.0f - 0.5f;
        float x0f = floorf(gpx), y0f = floorf(gpy);
        int x0 = (int)x0f, y0 = (int)y0f;
        float fx = gpx - x0f, fy = gpy - y0f;
        int x1 = x0 + 1, y1 = y0 + 1;
        float vx0 = (x0 >= 0 && x0 < 14) ? 1.0f : 0.0f;
        float vx1 = (x1 >= 0 && x1 < 14) ? 1.0f : 0.0f;
        float vy0 = (y0 >= 0 && y0 < 14) ? 1.0f : 0.0f;
        float vy1 = (y1 >= 0 && y1 < 14) ? 1.0f : 0.0f;
        int xc0 = min(max(x0, 0), 13), xc1 = min(max(x1, 0), 13);
        int yc0 = min(max(y0, 0), 13), yc1 = min(max(y1, 0), 13);
        g_tw[p] = make_float4((1.0f - fx) * (1.0f - fy) * vx0 * vy0,
                              fx * (1.0f - fy) * vx1 * vy0,
                              (1.0f - fx) * fy * vx0 * vy1,
                              fx * fy * vx1 * vy1);
        g_ti[p] = make_int4(yc0 * 14 + xc0, yc0 * 14 + xc1,
                            yc1 * 14 + xc0, yc1 * 14 + xc1);
    }
}

// ---------------------------------------------------------------------------
// Main fused kernel: one block (384 threads) per pose n.
// Compiled with __launch_bounds__(512) => hard 128-reg cap; launching 384
// threads keeps the register file request (12 warps x <=4096 regs) far from
// the 64K cliff that rejected R2/R3 launches.
// ---------------------------------------------------------------------------
// shared layout (floats):
//   dS    [0,455)      wigner d matrices (l-major)
//   cpow  [455,468)    cos(beta/2)^e
//   spow  [468,481)    sin(beta/2)^e
//   cA/sA [481,495)    cos/sin(m*alpha), m=0..6
//   cG/sG [495,509)    cos/sin(m*gamma)
//   Srot  [512,1492)   rotated spectrum, float2 {re,im} (49 x 10)
//   sigS  [1536,3496)  signal (10 x 196)
//   wS    [3500,3660)  deconv weights (10 x 16)
//   projS [3664,44624) projection (10 x 4096)
#define SMEM_FLOATS 44624
#define SMEM_BYTES  (SMEM_FLOATS * 4)

__global__ void __launch_bounds__(512)
decoder_kernel(const float* __restrict__ angles,
               const float* __restrict__ spectrum,
               const float* __restrict__ wt,
               const float* __restrict__ bt,
               float* __restrict__ out) {
    extern __shared__ float sm[];
    float*  dS   = sm;
    float*  cpow = sm + 455;
    float*  spow = sm + 468;
    float*  cA   = sm + 481;
    float*  sA   = sm + 488;
    float*  cG   = sm + 495;
    float*  sG   = sm + 502;
    float2* Srot = (float2*)(sm + 512);
    float*  sigS = sm + 1536;
    float*  wS   = sm + 3500;
    float*  projS = sm + 3664;

    const int n = blockIdx.x;
    const int tid = threadIdx.x;

    const float alpha = angles[3 * n + 0];
    const float beta  = angles[3 * n + 1];
    const float gamma = angles[3 * n + 2];
    const float bias = bt[0];

    // --- Phase A0: trig tables & weights ---
    if (tid < 7) {
        float s, c;
        sincosf((float)tid * alpha, &s, &c);
        cA[tid] = c; sA[tid] = s;
    } else if (tid < 14) {
        int m = tid - 7;
        float s, c;
        sincosf((float)m * gamma, &s, &c);
        cG[m] = c; sG[m] = s;
    } else if (tid == 14) {
        float sb, cb;
        sincosf(0.5f * beta, &sb, &cb);
        float cp = 1.0f, spw = 1.0f;
#pragma unroll
        for (int e = 0; e < 13; e++) {
            cpow[e] = cp; spow[e] = spw;
            cp *= cb; spw *= sb;
        }
    }
    if (tid < 160) wS[tid] = wt[tid];
    __syncthreads();

    // --- Phase A1: Wigner small-d matrices, one thread per (l,i,j) ---
    for (int t = tid; t < 455; t += BLOCK) {
        int l = (t >= 1) + (t >= 10) + (t >= 35) + (t >= 84) + (t >= 165) + (t >= 286);
        int n1 = 2 * l + 1;
        int loc = t - dloff(l);
        int base = slotbase(l) + loc * n1;
        float sum = 0.0f;
        for (int k = 0; k < n1; k++) {
            float cf = g_tcoef[base + k];
            int pc = (int)g_tpc[base + k];
            int ps = (int)g_tps[base + k];
            sum += cf * cpow[pc] * spow[ps];
        }
        dS[t] = sum;
    }
    __syncthreads();

    // --- Phase A2: complex Wigner-D rotate; (row, rep-half) per thread ---
    if (tid < 2 * MTOT) {
        int row = tid >> 1;
        int rbase = (tid & 1) * 5;
        int l = (row >= 1) + (row >= 4) + (row >= 9) + (row >= 16) + (row >= 25) + (row >= 36);
        int i = row - l * l;
        int mp = i - l;
        int n1 = 2 * l + 1;
        float camp = cA[mp < 0 ? -mp : mp];
        float samp = mp < 0 ? -sA[-mp] : sA[mp];
        float are[5], aim[5];
#pragma unroll
        for (int r = 0; r < 5; r++) { are[r] = 0.0f; aim[r] = 0.0f; }
        const float* drow = dS + dloff(l) + i * n1;
        for (int j = 0; j < n1; j++) {
            int m = j - l;
            float cg = cG[m < 0 ? -m : m];
            float sg = m < 0 ? -sG[-m] : sG[m];
            float cosang = camp * cg - samp * sg;
            float sinang = samp * cg + camp * sg;
            float dd = drow[j];
            float Dre = dd * cosang;
            float Dim = -dd * sinang;
            const float* sp2 = spectrum + (l * l + j) * 2 * NREP + 2 * rbase;
#pragma unroll
            for (int r = 0; r < 5; r++) {
                float sre = sp2[2 * r];
                float sim = sp2[2 * r + 1];
                are[r] += Dre * sre - Dim * sim;
                aim[r] += Dre * sim + Dim * sre;
            }
        }
#pragma unroll
        for (int r = 0; r < 5; r++)
            Srot[row * NREP + rbase + r] = make_float2(are[r], aim[r]);
    }
    __syncthreads();

    // --- Phase B: S2 inverse transform; (jk, rep-half) per thread ---
    for (int t = tid; t < 2 * NJK; t += BLOCK) {
        int jk = t >> 1;
        int rbase = (t & 1) * 5;
        float acc[5];
#pragma unroll
        for (int r = 0; r < 5; r++) acc[r] = 0.0f;
        for (int m = 0; m < MTOT; m++) {
            float2 y = g_Yc[m * NJK + jk];
            const float2* s = Srot + m * NREP + rbase;
#pragma unroll
            for (int r = 0; r < 5; r++) {
                float2 sv = s[r];
                acc[r] += sv.x * y.x - sv.y * y.y;
            }
        }
#pragma unroll
        for (int r = 0; r < 5; r++) sigS[(rbase + r) * NJK + jk] = acc[r];
    }
    __syncthreads();

    // --- Phase C: bilinear grid sample with precomputed packed taps ---
    for (int p = tid; p < NPTS; p += BLOCK) {
        float4 w = g_tw[p];
        int4 ii = g_ti[p];
#pragma unroll
        for (int r = 0; r < NREP; r++) {
            const float* s = sigS + r * NJK;
            projS[r * NPTS + p] = w.x * s[ii.x] + w.y * s[ii.y]
                                + w.z * s[ii.z] + w.w * s[ii.w];
        }
    }
    __syncthreads();

    // --- Phase D: ConvTranspose2d(10->1, k=4, s=2, p=1); 4x4 output tiles ---
    float* outn = out + (size_t)n * 16384;
    for (int t = tid; t < 1024; t += BLOCK) {
        int ty = t >> 5;            // 0..31 (4 output rows each)
        int tx = t & 31;            // 0..31 (4 output cols each)
        int p0 = 2 * ty;            // proj row base
        int q0 = 2 * tx;            // proj col base
        float acc[4][4];
#pragma unroll
        for (int dy = 0; dy < 4; dy++)
#pragma unroll
            for (int dx = 0; dx < 4; dx++) acc[dy][dx] = bias;

#pragma unroll
        for (int c = 0; c < NREP; c++) {
            float w[16];
#pragma unroll
            for (int kk = 0; kk < 16; kk++) w[kk] = wS[c * 16 + kk];
            float P[4][4];
#pragma unroll
            for (int yy = 0; yy < 4; yy++) {
                int iy = p0 - 1 + yy;
                bool vy = ((unsigned)iy < 64u);
                int iyc = vy ? iy : 0;
#pragma unroll
                for (int xx = 0; xx < 4; xx++) {
                    int ixx = q0 - 1 + xx;
                    bool v = vy && ((unsigned)ixx < 64u);
                    int ixc = v ? ixx : 0;
                    float val = projS[c * NPTS + iyc * 64 + ixc];
                    P[yy][xx] = v ? val : 0.0f;
                }
            }
#pragma unroll
            for (int dy = 0; dy < 4; dy++) {
                int pl = dy >> 1;
                int py = dy & 1;
                int ry0 = py ? pl + 2 : pl + 1;
                int ry1 = py ? pl + 1 : pl;
                int kya = py ? 0 : 1;
                int kyb = py ? 2 : 3;
#pragma unroll
                for (int dx = 0; dx < 4; dx++) {
                    int ql = dx >> 1;
                    int px = dx & 1;
                    int rx0 = px ? ql + 2 : ql + 1;
                    int rx1 = px ? ql + 1 : ql;
                    int kxa = px ? 0 : 1;
                    int kxb = px ? 2 : 3;
                    acc[dy][dx] += P[ry0][rx0] * w[kya * 4 + kxa]
                                 + P[ry0][rx1] * w[kya * 4 + kxb]
                                 + P[ry1][rx0] * w[kyb * 4 + kxa]
                                 + P[ry1][rx1] * w[kyb * 4 + kxb];
                }
            }
        }
#pragma unroll
        for (int dy = 0; dy < 4; dy++) {
            float4 v = make_float4(acc[dy][0], acc[dy][1], acc[dy][2], acc[dy][3]);
            *reinterpret_cast<float4*>(outn + (size_t)(4 * ty + dy) * 128 + 4 * tx) = v;
        }
    }
}

// ---------------------------------------------------------------------------
extern "C" void kernel_launch(void* const* d_in, const int* in_sizes, int n_in,
                              void* d_out, int out_size) {
    const float* angles   = (const float*)d_in[0];
    const float* spectrum = (const float*)d_in[1];
    const float* wt       = (const float*)d_in[2];
    const float* bt       = (const float*)d_in[3];
    float* out = (float*)d_out;

    cudaFuncSetAttribute(decoder_kernel,
                         cudaFuncAttributeMaxDynamicSharedMemorySize, SMEM_BYTES);

    setup_kernel<<<48, 256>>>();
    decoder_kernel<<<NPOSE, BLOCK, SMEM_BYTES>>>(angles, spectrum, wt, bt, out);
}

// round 6
// speedup vs baseline: 1.2144x; 1.0115x over previous
#include <cuda_runtime.h>
#include <math.h>

// ---------------------------------------------------------------------------
// ProjectionDecoder: Wigner rotate -> S2 ifft -> grid_sample -> convtranspose
// angles (2048,3) f32; spectrum (49,10,2) f32; wt (10,1,4,4) f32; bt (1) f32
// out (2048,1,128,128) f32
//
// R6: pose split into 2 blocks (output halves) so 2 blocks fit per SM
// (99 KB smem each) -> cross-block phase overlap (LDS-heavy C with FMA-heavy D).
// ---------------------------------------------------------------------------

#define NPOSE 2048
#define MTOT  49
#define NREP  10
#define NJK   196     // 14*14
#define NPTS  4096    // 64*64
#define NROWL 33      // proj rows held per half-block
#define NPTL  (NROWL * 64)   // 2112
#define NSLOT 4753    // sum (2l+1)^3, l=0..6
#define BLOCK 256

__device__ float       g_tcoef[NSLOT];
__device__ signed char g_tpc[NSLOT];
__device__ signed char g_tps[NSLOT];
__device__ float2      g_Yc[MTOT * NJK];   // {Yre, Yim}
__device__ float4      g_tw[NPTS];         // bilinear weights (validity folded)
__device__ int4        g_ti[NPTS];         // clamped gather indices into 14x14

__constant__ double c_fact[13] = {
    1.0, 1.0, 2.0, 6.0, 24.0, 120.0, 720.0, 5040.0,
    40320.0, 362880.0, 3628800.0, 39916800.0, 479001600.0 };

// slotbase[l] = sum_{k<l} (2k+1)^3 = l^2 (2 l^2 - 1)
__device__ __forceinline__ int slotbase(int l) { return l * l * (2 * l * l - 1); }
// dloff[l] = sum_{k<l} (2k+1)^2 = l(4l^2-1)/3
__device__ __forceinline__ int dloff(int l) { return l * (4 * l * l - 1) / 3; }

#define PI_F 3.14159265358979323846f

// ---------------------------------------------------------------------------
// Setup kernel: input-independent tables. fp32 transcendentals; fp64 only via
// the constant factorial table (no serial DP loops).
// ---------------------------------------------------------------------------
__global__ void setup_kernel() {
    int g = blockIdx.x * blockDim.x + threadIdx.x;

    if (g < NSLOT) {
        // Wigner term slot tables: slot -> (l, i=mp+l, j=m+l, k)
        int l = (g >= 1) + (g >= 28) + (g >= 153) + (g >= 496) + (g >= 1225) + (g >= 2556);
        int n1 = 2 * l + 1;
        int rem = g - slotbase(l);
        int i = rem / (n1 * n1);
        int j = (rem / n1) % n1;
        int k = rem % n1;
        int mp = i - l, m = j - l;
        int kmin = max(0, m - mp);
        int kmax = min(l + m, l - mp);
        float coef = 0.0f;
        int pc = 0, ps = 0;
        if (k >= kmin && k <= kmax) {
            double pref = sqrt(c_fact[l + mp] * c_fact[l - mp] * c_fact[l + m] * c_fact[l - m]);
            double c = pref / (c_fact[l + m - k] * c_fact[k] * c_fact[l - mp - k] * c_fact[mp - m + k]);
            if ((mp - m + k) & 1) c = -c;
            coef = (float)c;
            pc = 2 * l + m - mp - 2 * k;
            ps = mp - m + 2 * k;
        }
        g_tcoef[g] = coef;
        g_tpc[g] = (signed char)pc;
        g_tps[g] = (signed char)ps;
    } else if (g >= 5120 && g < 5120 + NJK) {
        // Spherical harmonic table Y (49, 14, 14) -- fp32
        int jk = g - 5120;
        int j = jk / 14, k = jk % 14;
        float beta = PI_F * (2.0f * j + 1.0f) / 28.0f;   // 4B = 28
        float x, sx;
        sincosf(beta, &sx, &x);
        float P[7][7];
#pragma unroll
        for (int a = 0; a < 7; a++)
#pragma unroll
            for (int b = 0; b < 7; b++) P[a][b] = 0.0f;
        P[0][0] = 1.0f;
        for (int m = 1; m <= 6; m++) P[m][m] = -(2.0f * m - 1.0f) * sx * P[m - 1][m - 1];
        for (int m = 0; m <= 6; m++) {
            if (m + 1 <= 6) P[m + 1][m] = (2.0f * m + 1.0f) * x * P[m][m];
            for (int l = m + 2; l <= 6; l++)
                P[l][m] = ((2.0f * l - 1.0f) * x * P[l - 1][m] - (l + m - 1.0f) * P[l - 2][m]) / (float)(l - m);
        }
        float alk = 2.0f * PI_F * (float)k / 14.0f;
        for (int l = 0; l <= 6; l++) {
            for (int m = 0; m <= l; m++) {
                float Nn = sqrtf((2.0f * l + 1.0f) / (4.0f * PI_F)
                                 * (float)(c_fact[l - m] / c_fact[l + m]));
                float pr = Nn * P[l][m];
                float sm_, cm_;
                sincosf((float)m * alk, &sm_, &cm_);
                float yre = pr * cm_;
                float yim = pr * sm_;
                g_Yc[(l * l + l + m) * NJK + jk] = make_float2(yre, yim);
                if (m > 0) {
                    float sgn = (m & 1) ? -1.0f : 1.0f;
                    g_Yc[(l * l + l - m) * NJK + jk] = make_float2(sgn * yre, -sgn * yim);
                }
            }
        }
    } else if (g >= 8192 && g < 8192 + NPTS) {
        // Orthographic grid -> packed bilinear taps (H = W = 14, a_c=False)
        int p = g - 8192;
        int iy = p / 64, ix = p % 64;
        float step = 1.6f / 63.0f;
        float yv = -0.8f + iy * step;
        float xv = -0.8f + ix * step;
        float rho = sqrtf(xv * xv + yv * yv);
        float th = asinf(fminf(rho, 1.0f));
        float ph = atan2f(yv, xv);
        float gx = ph / PI_F;
        float gy = 2.0f * th / PI_F - 1.0f;
        float gpx = (gx + 1.0f) * 7.0f - 0.5f;
        float gpy = (gy + 1.0f) * 7.0f - 0.5f;
        float x0f = floorf(gpx), y0f = floorf(gpy);
        int x0 = (int)x0f, y0 = (int)y0f;
        float fx = gpx - x0f, fy = gpy - y0f;
        int x1 = x0 + 1, y1 = y0 + 1;
        float vx0 = (x0 >= 0 && x0 < 14) ? 1.0f : 0.0f;
        float vx1 = (x1 >= 0 && x1 < 14) ? 1.0f : 0.0f;
        float vy0 = (y0 >= 0 && y0 < 14) ? 1.0f : 0.0f;
        float vy1 = (y1 >= 0 && y1 < 14) ? 1.0f : 0.0f;
        int xc0 = min(max(x0, 0), 13), xc1 = min(max(x1, 0), 13);
        int yc0 = min(max(y0, 0), 13), yc1 = min(max(y1, 0), 13);
        g_tw[p] = make_float4((1.0f - fx) * (1.0f - fy) * vx0 * vy0,
                              fx * (1.0f - fy) * vx1 * vy0,
                              (1.0f - fx) * fy * vx0 * vy1,
                              fx * fy * vx1 * vy1);
        g_ti[p] = make_int4(yc0 * 14 + xc0, yc0 * 14 + xc1,
                            yc1 * 14 + xc0, yc1 * 14 + xc1);
    }
}

// ---------------------------------------------------------------------------
// Main fused kernel: grid (2048, 2): blockIdx.x = pose, blockIdx.y = half.
// Each block: full rotate+ifft (cheap), then grid-sample + deconv for its
// 64 output rows (needs proj rows [31*h, 31*h+33)).
// ---------------------------------------------------------------------------
// shared layout (floats):
//   dS    [0,455)      wigner d matrices (l-major)
//   cpow  [455,468)  spow [468,481)  cA/sA [481,495)  cG/sG [495,509)
//   Srot  [512,1492)   rotated spectrum, float2 {re,im} (49 x 10)
//   sigS  [1536,3496)  signal (10 x 196)
//   wS    [3500,3660)  deconv weights (10 x 16)
//   projS [3664,24784) projection half (10 x 33 x 64)
#define SMEM_FLOATS 24784
#define SMEM_BYTES  (SMEM_FLOATS * 4)

__global__ void __launch_bounds__(BLOCK, 2)
decoder_kernel(const float* __restrict__ angles,
               const float* __restrict__ spectrum,
               const float* __restrict__ wt,
               const float* __restrict__ bt,
               float* __restrict__ out) {
    extern __shared__ float sm[];
    float*  dS   = sm;
    float*  cpow = sm + 455;
    float*  spow = sm + 468;
    float*  cA   = sm + 481;
    float*  sA   = sm + 488;
    float*  cG   = sm + 495;
    float*  sG   = sm + 502;
    float2* Srot = (float2*)(sm + 512);
    float*  sigS = sm + 1536;
    float*  wS   = sm + 3500;
    float*  projS = sm + 3664;

    const int n = blockIdx.x;
    const int h = blockIdx.y;         // output half: rows [64h, 64h+64)
    const int rowstart = 31 * h;      // first proj row held in projS
    const int tid = threadIdx.x;

    const float alpha = angles[3 * n + 0];
    const float beta  = angles[3 * n + 1];
    const float gamma = angles[3 * n + 2];
    const float bias = bt[0];

    // --- Phase A0: trig tables & weights ---
    if (tid < 7) {
        float s, c;
        sincosf((float)tid * alpha, &s, &c);
        cA[tid] = c; sA[tid] = s;
    } else if (tid < 14) {
        int m = tid - 7;
        float s, c;
        sincosf((float)m * gamma, &s, &c);
        cG[m] = c; sG[m] = s;
    } else if (tid == 14) {
        float sb, cb;
        sincosf(0.5f * beta, &sb, &cb);
        float cp = 1.0f, spw = 1.0f;
#pragma unroll
        for (int e = 0; e < 13; e++) {
            cpow[e] = cp; spow[e] = spw;
            cp *= cb; spw *= sb;
        }
    }
    if (tid < 160) wS[tid] = wt[tid];
    __syncthreads();

    // --- Phase A1: Wigner small-d matrices, one thread per (l,i,j) ---
    for (int t = tid; t < 455; t += BLOCK) {
        int l = (t >= 1) + (t >= 10) + (t >= 35) + (t >= 84) + (t >= 165) + (t >= 286);
        int n1 = 2 * l + 1;
        int loc = t - dloff(l);
        int base = slotbase(l) + loc * n1;
        float sum = 0.0f;
        for (int k = 0; k < n1; k++) {
            float cf = g_tcoef[base + k];
            int pc = (int)g_tpc[base + k];
            int ps = (int)g_tps[base + k];
            sum += cf * cpow[pc] * spow[ps];
        }
        dS[t] = sum;
    }
    __syncthreads();

    // --- Phase A2: complex Wigner-D rotate; (row, rep-half) per thread ---
    if (tid < 2 * MTOT) {
        int row = tid >> 1;
        int rbase = (tid & 1) * 5;
        int l = (row >= 1) + (row >= 4) + (row >= 9) + (row >= 16) + (row >= 25) + (row >= 36);
        int i = row - l * l;
        int mp = i - l;
        int n1 = 2 * l + 1;
        float camp = cA[mp < 0 ? -mp : mp];
        float samp = mp < 0 ? -sA[-mp] : sA[mp];
        float are[5], aim[5];
#pragma unroll
        for (int r = 0; r < 5; r++) { are[r] = 0.0f; aim[r] = 0.0f; }
        const float* drow = dS + dloff(l) + i * n1;
        for (int j = 0; j < n1; j++) {
            int m = j - l;
            float cg = cG[m < 0 ? -m : m];
            float sg = m < 0 ? -sG[-m] : sG[m];
            float cosang = camp * cg - samp * sg;
            float sinang = samp * cg + camp * sg;
            float dd = drow[j];
            float Dre = dd * cosang;
            float Dim = -dd * sinang;
            const float* sp2 = spectrum + (l * l + j) * 2 * NREP + 2 * rbase;
#pragma unroll
            for (int r = 0; r < 5; r++) {
                float sre = sp2[2 * r];
                float sim = sp2[2 * r + 1];
                are[r] += Dre * sre - Dim * sim;
                aim[r] += Dre * sim + Dim * sre;
            }
        }
#pragma unroll
        for (int r = 0; r < 5; r++)
            Srot[row * NREP + rbase + r] = make_float2(are[r], aim[r]);
    }
    __syncthreads();

    // --- Phase B: S2 inverse transform; (jk, rep-half) per thread ---
    for (int t = tid; t < 2 * NJK; t += BLOCK) {
        int jk = t >> 1;
        int rbase = (t & 1) * 5;
        float acc[5];
#pragma unroll
        for (int r = 0; r < 5; r++) acc[r] = 0.0f;
        for (int m = 0; m < MTOT; m++) {
            float2 y = g_Yc[m * NJK + jk];
            const float2* s = Srot + m * NREP + rbase;
#pragma unroll
            for (int r = 0; r < 5; r++) {
                float2 sv = s[r];
                acc[r] += sv.x * y.x - sv.y * y.y;
            }
        }
#pragma unroll
        for (int r = 0; r < 5; r++) sigS[(rbase + r) * NJK + jk] = acc[r];
    }
    __syncthreads();

    // --- Phase C: bilinear grid sample for this half's 33 proj rows ---
    for (int p = tid; p < NPTL; p += BLOCK) {
        int gidx = rowstart * 64 + p;      // global proj point
        float4 w = g_tw[gidx];
        int4 ii = g_ti[gidx];
#pragma unroll
        for (int r = 0; r < NREP; r++) {
            const float* s = sigS + r * NJK;
            projS[r * NPTL + p] = w.x * s[ii.x] + w.y * s[ii.y]
                                + w.z * s[ii.z] + w.w * s[ii.w];
        }
    }
    __syncthreads();

    // --- Phase D: ConvTranspose2d; 512 tiles of 4x4 outputs, 2 iters ---
    float* outn = out + (size_t)n * 16384;
#pragma unroll
    for (int it = 0; it < 2; it++) {
        int t = tid + it * BLOCK;   // 0..511
        int tyl = t >> 5;           // 0..15 local tile row
        int tx = t & 31;            // 0..31
        int ty = h * 16 + tyl;      // global tile row (4 out rows each)
        int p0 = 2 * ty;            // global proj row base
        int q0 = 2 * tx;            // proj col base
        float acc[4][4];
#pragma unroll
        for (int dy = 0; dy < 4; dy++)
#pragma unroll
            for (int dx = 0; dx < 4; dx++) acc[dy][dx] = bias;

#pragma unroll
        for (int c = 0; c < NREP; c++) {
            float w[16];
#pragma unroll
            for (int kk = 0; kk < 16; kk++) w[kk] = wS[c * 16 + kk];
            float P[4][4];
#pragma unroll
            for (int yy = 0; yy < 4; yy++) {
                int grow = p0 - 1 + yy;                 // global proj row
                bool vy = ((unsigned)grow < 64u);
                int lr = grow - rowstart;               // local row in projS
                int lrc = vy ? lr : 0;
#pragma unroll
                for (int xx = 0; xx < 4; xx++) {
                    int ixx = q0 - 1 + xx;
                    bool v = vy && ((unsigned)ixx < 64u);
                    int ixc = v ? ixx : 0;
                    float val = projS[c * NPTL + lrc * 64 + ixc];
                    P[yy][xx] = v ? val : 0.0f;
                }
            }
#pragma unroll
            for (int dy = 0; dy < 4; dy++) {
                int pl = dy >> 1;
                int py = dy & 1;
                int ry0 = py ? pl + 2 : pl + 1;
                int ry1 = py ? pl + 1 : pl;
                int kya = py ? 0 : 1;
                int kyb = py ? 2 : 3;
#pragma unroll
                for (int dx = 0; dx < 4; dx++) {
                    int ql = dx >> 1;
                    int px = dx & 1;
                    int rx0 = px ? ql + 2 : ql + 1;
                    int rx1 = px ? ql + 1 : ql;
                    int kxa = px ? 0 : 1;
                    int kxb = px ? 2 : 3;
                    acc[dy][dx] += P[ry0][rx0] * w[kya * 4 + kxa]
                                 + P[ry0][rx1] * w[kya * 4 + kxb]
                                 + P[ry1][rx0] * w[kyb * 4 + kxa]
                                 + P[ry1][rx1] * w[kyb * 4 + kxb];
                }
            }
        }
#pragma unroll
        for (int dy = 0; dy < 4; dy++) {
            float4 v = make_float4(acc[dy][0], acc[dy][1], acc[dy][2], acc[dy][3]);
            *reinterpret_cast<float4*>(outn + (size_t)(4 * ty + dy) * 128 + 4 * tx) = v;
        }
    }
}

// ---------------------------------------------------------------------------
extern "C" void kernel_launch(void* const* d_in, const int* in_sizes, int n_in,
                              void* d_out, int out_size) {
    const float* angles   = (const float*)d_in[0];
    const float* spectrum = (const float*)d_in[1];
    const float* wt       = (const float*)d_in[2];
    const float* bt       = (const float*)d_in[3];
    float* out = (float*)d_out;

    cudaFuncSetAttribute(decoder_kernel,
                         cudaFuncAttributeMaxDynamicSharedMemorySize, SMEM_BYTES);

    setup_kernel<<<48, 256>>>();
    dim3 grid(NPOSE, 2);
    decoder_kernel<<<grid, BLOCK, SMEM_BYTES>>>(angles, spectrum, wt, bt, out);
}

// round 8
// speedup vs baseline: 1.7012x; 1.4008x over previous
#include <cuda_runtime.h>
#include <cuda_fp16.h>
#include <math.h>

// ---------------------------------------------------------------------------
// ProjectionDecoder: Wigner rotate -> S2 ifft -> grid_sample -> convtranspose
// angles (2048,3) f32; spectrum (49,10,2) f32; wt (10,1,4,4) f32; bt (1) f32
// out (2048,1,128,128) f32
//
// R8: sig fp32 parity-pair copies (paired LDS.64 gathers), proj fp16 padded
// (halved D-phase smem traffic, no predication). One block/pose, 2 blocks/SM.
// Setup grid FIXED to cover the full tap table (R7 bug: taps ended at 12416
// but only 12288 setup threads ran).
// ---------------------------------------------------------------------------

#define NPOSE 2048
#define MTOT  49
#define NREP  10
#define NJK   196     // 14*14
#define NSLOT 4753    // sum (2l+1)^3, l=0..6
#define BLOCK 256

// sig: [copy(2)][r(10)][row(14)][8 pairs] of float2
#define SIG_COPY_P   1120      // 10*14*8 pairs per copy
#define SIG_R_P      112       // 14*8
#define SIG_TOT_P    2240
// proj: [c(10)][storedrow(66)][33 words] of half2
#define PROJ_ROW_W   33
#define PROJ_C_W     (66 * PROJ_ROW_W)   // 2178
#define PROJ_TOT_W   (NREP * PROJ_C_W)   // 21780

#define NTAP  (64 * 66)   // tap entries indexed [projrow][stored h]

__device__ float       g_tcoef[NSLOT];
__device__ signed char g_tpc[NSLOT];
__device__ signed char g_tps[NSLOT];
__device__ float2      g_Yc[MTOT * NJK];   // {Yre, Yim}
__device__ float4      g_tpw[NTAP];        // (wa0, wb0, wa1, wb1)
__device__ int2        g_tpo[NTAP];        // pair offsets (row0, row1), excl. r term

__constant__ double c_fact[13] = {
    1.0, 1.0, 2.0, 6.0, 24.0, 120.0, 720.0, 5040.0,
    40320.0, 362880.0, 3628800.0, 39916800.0, 479001600.0 };

__device__ __forceinline__ int slotbase(int l) { return l * l * (2 * l * l - 1); }
__device__ __forceinline__ int dloff(int l) { return l * (4 * l * l - 1) / 3; }

#define PI_F 3.14159265358979323846f

// ---------------------------------------------------------------------------
// Setup kernel: input-independent tables.
// ---------------------------------------------------------------------------
__global__ void setup_kernel() {
    int g = blockIdx.x * blockDim.x + threadIdx.x;

    if (g < NSLOT) {
        int l = (g >= 1) + (g >= 28) + (g >= 153) + (g >= 496) + (g >= 1225) + (g >= 2556);
        int n1 = 2 * l + 1;
        int rem = g - slotbase(l);
        int i = rem / (n1 * n1);
        int j = (rem / n1) % n1;
        int k = rem % n1;
        int mp = i - l, m = j - l;
        int kmin = max(0, m - mp);
        int kmax = min(l + m, l - mp);
        float coef = 0.0f;
        int pc = 0, ps = 0;
        if (k >= kmin && k <= kmax) {
            double pref = sqrt(c_fact[l + mp] * c_fact[l - mp] * c_fact[l + m] * c_fact[l - m]);
            double c = pref / (c_fact[l + m - k] * c_fact[k] * c_fact[l - mp - k] * c_fact[mp - m + k]);
            if ((mp - m + k) & 1) c = -c;
            coef = (float)c;
            pc = 2 * l + m - mp - 2 * k;
            ps = mp - m + 2 * k;
        }
        g_tcoef[g] = coef;
        g_tpc[g] = (signed char)pc;
        g_tps[g] = (signed char)ps;
    } else if (g >= 5120 && g < 5120 + NJK) {
        // Spherical harmonic table Y (49, 14, 14)
        int jk = g - 5120;
        int j = jk / 14, k = jk % 14;
        float beta = PI_F * (2.0f * j + 1.0f) / 28.0f;
        float x, sx;
        sincosf(beta, &sx, &x);
        float P[7][7];
#pragma unroll
        for (int a = 0; a < 7; a++)
#pragma unroll
            for (int b = 0; b < 7; b++) P[a][b] = 0.0f;
        P[0][0] = 1.0f;
        for (int m = 1; m <= 6; m++) P[m][m] = -(2.0f * m - 1.0f) * sx * P[m - 1][m - 1];
        for (int m = 0; m <= 6; m++) {
            if (m + 1 <= 6) P[m + 1][m] = (2.0f * m + 1.0f) * x * P[m][m];
            for (int l = m + 2; l <= 6; l++)
                P[l][m] = ((2.0f * l - 1.0f) * x * P[l - 1][m] - (l + m - 1.0f) * P[l - 2][m]) / (float)(l - m);
        }
        float alk = 2.0f * PI_F * (float)k / 14.0f;
        for (int l = 0; l <= 6; l++) {
            for (int m = 0; m <= l; m++) {
                float Nn = sqrtf((2.0f * l + 1.0f) / (4.0f * PI_F)
                                 * (float)(c_fact[l - m] / c_fact[l + m]));
                float pr = Nn * P[l][m];
                float sm_, cm_;
                sincosf((float)m * alk, &sm_, &cm_);
                float yre = pr * cm_;
                float yim = pr * sm_;
                g_Yc[(l * l + l + m) * NJK + jk] = make_float2(yre, yim);
                if (m > 0) {
                    float sgn = (m & 1) ? -1.0f : 1.0f;
                    g_Yc[(l * l + l - m) * NJK + jk] = make_float2(sgn * yre, -sgn * yim);
                }
            }
        }
    } else if (g >= 8192 && g < 8192 + NTAP) {
        // Tap table entry for (proj row, stored h). col = h - 1.
        int idx = g - 8192;
        int row = idx / 66;
        int h = idx % 66;
        int col = h - 1;
        float4 w4 = make_float4(0.f, 0.f, 0.f, 0.f);
        int2 o2 = make_int2(0, 0);
        if (col >= 0 && col < 64) {
            float step = 1.6f / 63.0f;
            float yv = -0.8f + row * step;
            float xv = -0.8f + col * step;
            float rho = sqrtf(xv * xv + yv * yv);
            float th = asinf(fminf(rho, 1.0f));
            float ph = atan2f(yv, xv);
            float gx = ph / PI_F;
            float gy = 2.0f * th / PI_F - 1.0f;
            float gpx = (gx + 1.0f) * 7.0f - 0.5f;
            float gpy = (gy + 1.0f) * 7.0f - 0.5f;
            float x0f = floorf(gpx), y0f = floorf(gpy);
            int x0 = (int)x0f, y0 = (int)y0f;
            float fx = gpx - x0f, fy = gpy - y0f;
            float wx0 = 1.0f - fx, wx1 = fx;
            float wy[2] = {1.0f - fy, fy};
            int offs[2] = {0, 0};
            float wa[2] = {0.f, 0.f}, wb[2] = {0.f, 0.f};
#pragma unroll
            for (int rr = 0; rr < 2; rr++) {
                int y = y0 + rr;
                if (y >= 0 && y < 14) {
                    if (x0 >= 0 && x0 <= 13) {
                        int parity = x0 & 1;
                        int hh = x0 >> 1;
                        offs[rr] = parity * SIG_COPY_P + y * 8 + hh;
                        wa[rr] = wx0 * wy[rr];
                        wb[rr] = (x0 == 13) ? 0.0f : wx1 * wy[rr];
                    } else if (x0 == -1) {
                        // pair (col0, col1): elem0 = s[x1=0]
                        offs[rr] = y * 8;           // even copy, pair 0
                        wa[rr] = wx1 * wy[rr];
                        wb[rr] = 0.0f;
                    }
                }
            }
            w4 = make_float4(wa[0], wb[0], wa[1], wb[1]);
            o2 = make_int2(offs[0], offs[1]);
        }
        g_tpw[idx] = w4;
        g_tpo[idx] = o2;
    }
}

// ---------------------------------------------------------------------------
// Main fused kernel: one block (256 threads) per pose n, 2 blocks/SM.
// smem word layout (4B words):
//   dS    [0,455)     cpow [455,468)  spow [468,481)
//   cA [481,488) sA [488,495) cG [495,502) sG [502,509)
//   wS    [512,672)   deconv weights (10 x 16)
//   Srot  [672,1652)  rotated spectrum float2 (49 x 10)
//   sigF  [1652,6132) 2 parity copies of float pairs (float2-addressable)
//   proj  [6132,27912) fp16 padded projection, half2 words
#define SIG_OFF  1652
#define PROJ_OFF 6132
#define SMEM_WORDS 27912
#define SMEM_BYTES (SMEM_WORDS * 4)

__global__ void __launch_bounds__(BLOCK, 2)
decoder_kernel(const float* __restrict__ angles,
               const float* __restrict__ spectrum,
               const float* __restrict__ wt,
               const float* __restrict__ bt,
               float* __restrict__ out) {
    extern __shared__ float sm[];
    float*  dS   = sm;
    float*  cpow = sm + 455;
    float*  spow = sm + 468;
    float*  cA   = sm + 481;
    float*  sA   = sm + 488;
    float*  cG   = sm + 495;
    float*  sG   = sm + 502;
    float*  wS   = sm + 512;
    float2* Srot = (float2*)(sm + 672);
    float*  sigF = sm + SIG_OFF;               // float view (pair = 2 floats)
    float2* sigP = (float2*)(sm + SIG_OFF);    // pair view
    unsigned int* projW = (unsigned int*)(sm + PROJ_OFF);

    const int n = blockIdx.x;
    const int tid = threadIdx.x;

    const float alpha = angles[3 * n + 0];
    const float beta  = angles[3 * n + 1];
    const float gamma = angles[3 * n + 2];
    const float bias = bt[0];

    // --- Phase A0: trig tables, weights, zero sig copies ---
    if (tid < 7) {
        float s, c;
        sincosf((float)tid * alpha, &s, &c);
        cA[tid] = c; sA[tid] = s;
    } else if (tid < 14) {
        int m = tid - 7;
        float s, c;
        sincosf((float)m * gamma, &s, &c);
        cG[m] = c; sG[m] = s;
    } else if (tid == 14) {
        float sb, cb;
        sincosf(0.5f * beta, &sb, &cb);
        float cp = 1.0f, spw = 1.0f;
#pragma unroll
        for (int e = 0; e < 13; e++) {
            cpow[e] = cp; spow[e] = spw;
            cp *= cb; spw *= sb;
        }
    }
    if (tid < 160) wS[tid] = wt[tid];
    for (int i = tid; i < 2 * SIG_TOT_P; i += BLOCK) sigF[i] = 0.0f;
    __syncthreads();

    // --- Phase A1: Wigner small-d matrices ---
    for (int t = tid; t < 455; t += BLOCK) {
        int l = (t >= 1) + (t >= 10) + (t >= 35) + (t >= 84) + (t >= 165) + (t >= 286);
        int n1 = 2 * l + 1;
        int loc = t - dloff(l);
        int base = slotbase(l) + loc * n1;
        float sum = 0.0f;
        for (int k = 0; k < n1; k++) {
            float cf = g_tcoef[base + k];
            int pc = (int)g_tpc[base + k];
            int ps = (int)g_tps[base + k];
            sum += cf * cpow[pc] * spow[ps];
        }
        dS[t] = sum;
    }
    __syncthreads();

    // --- Phase A2: complex Wigner-D rotate ---
    if (tid < 2 * MTOT) {
        int row = tid >> 1;
        int rbase = (tid & 1) * 5;
        int l = (row >= 1) + (row >= 4) + (row >= 9) + (row >= 16) + (row >= 25) + (row >= 36);
        int i = row - l * l;
        int mp = i - l;
        int n1 = 2 * l + 1;
        float camp = cA[mp < 0 ? -mp : mp];
        float samp = mp < 0 ? -sA[-mp] : sA[mp];
        float are[5], aim[5];
#pragma unroll
        for (int r = 0; r < 5; r++) { are[r] = 0.0f; aim[r] = 0.0f; }
        const float* drow = dS + dloff(l) + i * n1;
        for (int j = 0; j < n1; j++) {
            int m = j - l;
            float cg = cG[m < 0 ? -m : m];
            float sg = m < 0 ? -sG[-m] : sG[m];
            float cosang = camp * cg - samp * sg;
            float sinang = samp * cg + camp * sg;
            float dd = drow[j];
            float Dre = dd * cosang;
            float Dim = -dd * sinang;
            const float* sp2 = spectrum + (l * l + j) * 2 * NREP + 2 * rbase;
#pragma unroll
            for (int r = 0; r < 5; r++) {
                float sre = sp2[2 * r];
                float sim = sp2[2 * r + 1];
                are[r] += Dre * sre - Dim * sim;
                aim[r] += Dre * sim + Dim * sre;
            }
        }
#pragma unroll
        for (int r = 0; r < 5; r++)
            Srot[row * NREP + rbase + r] = make_float2(are[r], aim[r]);
    }
    __syncthreads();

    // --- Phase B: S2 inverse transform -> fp32 parity copies ---
    for (int t = tid; t < 2 * NJK; t += BLOCK) {
        int jk = t >> 1;
        int rbase = (t & 1) * 5;
        float acc[5];
#pragma unroll
        for (int r = 0; r < 5; r++) acc[r] = 0.0f;
        for (int m = 0; m < MTOT; m++) {
            float2 y = g_Yc[m * NJK + jk];
            const float2* s = Srot + m * NREP + rbase;
#pragma unroll
            for (int r = 0; r < 5; r++) {
                float2 sv = s[r];
                acc[r] += sv.x * y.x - sv.y * y.y;
            }
        }
        int j = jk / 14, k = jk % 14;
#pragma unroll
        for (int r = 0; r < 5; r++) {
            int rr = rbase + r;
            float v = acc[r];
            // even copy: float index (rr*112 + j*8)*2 + k
            sigF[(rr * SIG_R_P + j * 8) * 2 + k] = v;
            // odd copy: float index (COPY + rr*112 + j*8)*2 + (k-1)
            if (k > 0)
                sigF[(SIG_COPY_P + rr * SIG_R_P + j * 8) * 2 + (k - 1)] = v;
        }
    }
    __syncthreads();

    // --- Phase C: bilinear grid sample -> padded fp16 proj ---
    // task = stored word (srow 0..65, w 0..32); covers proj cols (2w-1, 2w)
    for (int task = tid; task < 66 * PROJ_ROW_W; task += BLOCK) {
        int srow = task / PROJ_ROW_W;
        int w = task - srow * PROJ_ROW_W;
        unsigned int pofs = (unsigned int)(srow * PROJ_ROW_W + w);
        if (srow == 0 || srow == 65) {
#pragma unroll
            for (int c = 0; c < NREP; c++) projW[c * PROJ_C_W + pofs] = 0u;
            continue;
        }
        int row = srow - 1;
        int e = row * 66 + 2 * w;
        float4 wA = g_tpw[e];
        float4 wB = g_tpw[e + 1];
        int2 oA = g_tpo[e];
        int2 oB = g_tpo[e + 1];
#pragma unroll
        for (int c = 0; c < NREP; c++) {
            int rofs = c * SIG_R_P;
            float2 a0 = sigP[oA.x + rofs];
            float2 a1 = sigP[oA.y + rofs];
            float v0 = wA.x * a0.x + wA.y * a0.y + wA.z * a1.x + wA.w * a1.y;
            float2 b0 = sigP[oB.x + rofs];
            float2 b1 = sigP[oB.y + rofs];
            float v1 = wB.x * b0.x + wB.y * b0.y + wB.z * b1.x + wB.w * b1.y;
            __half2 pv = __floats2half2_rn(v0, v1);
            projW[c * PROJ_C_W + pofs] = *(unsigned int*)&pv;
        }
    }
    __syncthreads();

    // --- Phase D: ConvTranspose2d(10->1,k=4,s=2,p=1), channel-outer ---
    // 1024 tiles of 4x4 outputs; this thread owns tiles tid, tid+256, ...
    float acc[4][4][4];
#pragma unroll
    for (int t4 = 0; t4 < 4; t4++)
#pragma unroll
        for (int dy = 0; dy < 4; dy++)
#pragma unroll
            for (int dx = 0; dx < 4; dx++) acc[t4][dy][dx] = bias;

#pragma unroll
    for (int c = 0; c < NREP; c++) {
        float w[16];
#pragma unroll
        for (int kk = 0; kk < 16; kk++) w[kk] = wS[c * 16 + kk];
#pragma unroll
        for (int t4 = 0; t4 < 4; t4++) {
            int t = tid + t4 * BLOCK;
            int ty = t >> 5;
            int tx = t & 31;
            float P[4][4];
#pragma unroll
            for (int yy = 0; yy < 4; yy++) {
                unsigned int base = (unsigned int)((c * 66 + 2 * ty + yy) * PROJ_ROW_W + tx);
                float2 ab = __half22float2(*(__half2*)&projW[base]);
                float2 cd = __half22float2(*(__half2*)&projW[base + 1]);
                P[yy][0] = ab.x; P[yy][1] = ab.y;
                P[yy][2] = cd.x; P[yy][3] = cd.y;
            }
#pragma unroll
            for (int dy = 0; dy < 4; dy++) {
                int pl = dy >> 1;
                int py = dy & 1;
                int ry0 = py ? pl + 2 : pl + 1;
                int ry1 = py ? pl + 1 : pl;
                int kya = py ? 0 : 1;
                int kyb = py ? 2 : 3;
#pragma unroll
                for (int dx = 0; dx < 4; dx++) {
                    int ql = dx >> 1;
                    int px = dx & 1;
                    int rx0 = px ? ql + 2 : ql + 1;
                    int rx1 = px ? ql + 1 : ql;
                    int kxa = px ? 0 : 1;
                    int kxb = px ? 2 : 3;
                    acc[t4][dy][dx] += P[ry0][rx0] * w[kya * 4 + kxa]
                                     + P[ry0][rx1] * w[kya * 4 + kxb]
                                     + P[ry1][rx0] * w[kyb * 4 + kxa]
                                     + P[ry1][rx1] * w[kyb * 4 + kxb];
                }
            }
        }
    }

    float* outn = out + (size_t)n * 16384;
#pragma unroll
    for (int t4 = 0; t4 < 4; t4++) {
        int t = tid + t4 * BLOCK;
        int ty = t >> 5;
        int tx = t & 31;
#pragma unroll
        for (int dy = 0; dy < 4; dy++) {
            float4 v = make_float4(acc[t4][dy][0], acc[t4][dy][1],
                                   acc[t4][dy][2], acc[t4][dy][3]);
            *reinterpret_cast<float4*>(outn + (size_t)(4 * ty + dy) * 128 + 4 * tx) = v;
        }
    }
}

// ---------------------------------------------------------------------------
extern "C" void kernel_launch(void* const* d_in, const int* in_sizes, int n_in,
                              void* d_out, int out_size) {
    const float* angles   = (const float*)d_in[0];
    const float* spectrum = (const float*)d_in[1];
    const float* wt       = (const float*)d_in[2];
    const float* bt       = (const float*)d_in[3];
    float* out = (float*)d_out;

    cudaFuncSetAttribute(decoder_kernel,
                         cudaFuncAttributeMaxDynamicSharedMemorySize, SMEM_BYTES);

    // 64 blocks x 256 = 16384 threads: covers taps up to 8192+4224=12416.
    setup_kernel<<<64, 256>>>();
    decoder_kernel<<<NPOSE, BLOCK, SMEM_BYTES>>>(angles, spectrum, wt, bt, out);
}

// round 9
// speedup vs baseline: 1.7492x; 1.0282x over previous
#include <cuda_runtime.h>
#include <cuda_fp16.h>
#include <math.h>

// ---------------------------------------------------------------------------
// ProjectionDecoder: Wigner rotate -> S2 ifft -> grid_sample -> convtranspose
// angles (2048,3) f32; spectrum (49,10,2) f32; wt (10,1,4,4) f32; bt (1) f32
// out (2048,1,128,128) f32
//
// R9: 3 blocks/SM. Channel-grouped proj (2 passes x 5 ch) shrinks smem to
// ~67 KB; phase D is tile-sequential with global RMW merge (no 64-reg acc);
// deconv weights/bias in __constant__ (no LDS for w, fewer regs).
// ---------------------------------------------------------------------------

#define NPOSE 2048
#define MTOT  49
#define NREP  10
#define NGRP  5       // channels per proj pass
#define NJK   196     // 14*14
#define NSLOT 4753    // sum (2l+1)^3, l=0..6
#define BLOCK 256

// sig: [copy(2)][r(10)][row(14)][8 pairs] of float2
#define SIG_COPY_P   1120      // pairs per copy
#define SIG_R_P      112       // 14*8
#define SIG_TOT_P    2240
// proj: [cl(5)][storedrow(66)][33 words] of half2
#define PROJ_ROW_W   33
#define PROJ_C_W     (66 * PROJ_ROW_W)   // 2178
#define PROJ_TOT_W   (NGRP * PROJ_C_W)   // 10890

#define NTAP  (64 * 66)   // tap entries indexed [projrow][stored h]

__device__ float       g_tcoef[NSLOT];
__device__ signed char g_tpc[NSLOT];
__device__ signed char g_tps[NSLOT];
__device__ float2      g_Yc[MTOT * NJK];   // {Yre, Yim}
__device__ float4      g_tpw[NTAP];        // (wa0, wb0, wa1, wb1)
__device__ int2        g_tpo[NTAP];        // pair offsets (row0, row1), excl. r term

__constant__ float  c_wt[160];   // deconv weights (10 x 16)
__constant__ float  c_bt[1];     // bias
__constant__ double c_fact[13] = {
    1.0, 1.0, 2.0, 6.0, 24.0, 120.0, 720.0, 5040.0,
    40320.0, 362880.0, 3628800.0, 39916800.0, 479001600.0 };

__device__ __forceinline__ int slotbase(int l) { return l * l * (2 * l * l - 1); }
__device__ __forceinline__ int dloff(int l) { return l * (4 * l * l - 1) / 3; }

#define PI_F 3.14159265358979323846f

// ---------------------------------------------------------------------------
// Setup kernel: input-independent tables.
// ---------------------------------------------------------------------------
__global__ void setup_kernel() {
    int g = blockIdx.x * blockDim.x + threadIdx.x;

    if (g < NSLOT) {
        int l = (g >= 1) + (g >= 28) + (g >= 153) + (g >= 496) + (g >= 1225) + (g >= 2556);
        int n1 = 2 * l + 1;
        int rem = g - slotbase(l);
        int i = rem / (n1 * n1);
        int j = (rem / n1) % n1;
        int k = rem % n1;
        int mp = i - l, m = j - l;
        int kmin = max(0, m - mp);
        int kmax = min(l + m, l - mp);
        float coef = 0.0f;
        int pc = 0, ps = 0;
        if (k >= kmin && k <= kmax) {
            double pref = sqrt(c_fact[l + mp] * c_fact[l - mp] * c_fact[l + m] * c_fact[l - m]);
            double c = pref / (c_fact[l + m - k] * c_fact[k] * c_fact[l - mp - k] * c_fact[mp - m + k]);
            if ((mp - m + k) & 1) c = -c;
            coef = (float)c;
            pc = 2 * l + m - mp - 2 * k;
            ps = mp - m + 2 * k;
        }
        g_tcoef[g] = coef;
        g_tpc[g] = (signed char)pc;
        g_tps[g] = (signed char)ps;
    } else if (g >= 5120 && g < 5120 + NJK) {
        // Spherical harmonic table Y (49, 14, 14)
        int jk = g - 5120;
        int j = jk / 14, k = jk % 14;
        float beta = PI_F * (2.0f * j + 1.0f) / 28.0f;
        float x, sx;
        sincosf(beta, &sx, &x);
        float P[7][7];
#pragma unroll
        for (int a = 0; a < 7; a++)
#pragma unroll
            for (int b = 0; b < 7; b++) P[a][b] = 0.0f;
        P[0][0] = 1.0f;
        for (int m = 1; m <= 6; m++) P[m][m] = -(2.0f * m - 1.0f) * sx * P[m - 1][m - 1];
        for (int m = 0; m <= 6; m++) {
            if (m + 1 <= 6) P[m + 1][m] = (2.0f * m + 1.0f) * x * P[m][m];
            for (int l = m + 2; l <= 6; l++)
                P[l][m] = ((2.0f * l - 1.0f) * x * P[l - 1][m] - (l + m - 1.0f) * P[l - 2][m]) / (float)(l - m);
        }
        float alk = 2.0f * PI_F * (float)k / 14.0f;
        for (int l = 0; l <= 6; l++) {
            for (int m = 0; m <= l; m++) {
                float Nn = sqrtf((2.0f * l + 1.0f) / (4.0f * PI_F)
                                 * (float)(c_fact[l - m] / c_fact[l + m]));
                float pr = Nn * P[l][m];
                float sm_, cm_;
                sincosf((float)m * alk, &sm_, &cm_);
                float yre = pr * cm_;
                float yim = pr * sm_;
                g_Yc[(l * l + l + m) * NJK + jk] = make_float2(yre, yim);
                if (m > 0) {
                    float sgn = (m & 1) ? -1.0f : 1.0f;
                    g_Yc[(l * l + l - m) * NJK + jk] = make_float2(sgn * yre, -sgn * yim);
                }
            }
        }
    } else if (g >= 8192 && g < 8192 + NTAP) {
        // Tap table entry for (proj row, stored h). col = h - 1.
        int idx = g - 8192;
        int row = idx / 66;
        int h = idx % 66;
        int col = h - 1;
        float4 w4 = make_float4(0.f, 0.f, 0.f, 0.f);
        int2 o2 = make_int2(0, 0);
        if (col >= 0 && col < 64) {
            float step = 1.6f / 63.0f;
            float yv = -0.8f + row * step;
            float xv = -0.8f + col * step;
            float rho = sqrtf(xv * xv + yv * yv);
            float th = asinf(fminf(rho, 1.0f));
            float ph = atan2f(yv, xv);
            float gx = ph / PI_F;
            float gy = 2.0f * th / PI_F - 1.0f;
            float gpx = (gx + 1.0f) * 7.0f - 0.5f;
            float gpy = (gy + 1.0f) * 7.0f - 0.5f;
            float x0f = floorf(gpx), y0f = floorf(gpy);
            int x0 = (int)x0f, y0 = (int)y0f;
            float fx = gpx - x0f, fy = gpy - y0f;
            float wx0 = 1.0f - fx, wx1 = fx;
            float wy[2] = {1.0f - fy, fy};
            int offs[2] = {0, 0};
            float wa[2] = {0.f, 0.f}, wb[2] = {0.f, 0.f};
#pragma unroll
            for (int rr = 0; rr < 2; rr++) {
                int y = y0 + rr;
                if (y >= 0 && y < 14) {
                    if (x0 >= 0 && x0 <= 13) {
                        int parity = x0 & 1;
                        int hh = x0 >> 1;
                        offs[rr] = parity * SIG_COPY_P + y * 8 + hh;
                        wa[rr] = wx0 * wy[rr];
                        wb[rr] = (x0 == 13) ? 0.0f : wx1 * wy[rr];
                    } else if (x0 == -1) {
                        offs[rr] = y * 8;           // even copy, pair 0
                        wa[rr] = wx1 * wy[rr];
                        wb[rr] = 0.0f;
                    }
                }
            }
            w4 = make_float4(wa[0], wb[0], wa[1], wb[1]);
            o2 = make_int2(offs[0], offs[1]);
        }
        g_tpw[idx] = w4;
        g_tpo[idx] = o2;
    }
}

// ---------------------------------------------------------------------------
// Main fused kernel: one block (256 threads) per pose n, 3 blocks/SM.
// smem word layout (4B words):
//   dS [0,455)  cpow [455,468)  spow [468,481)
//   cA [481,488) sA [488,495) cG [495,502) sG [502,509)
//   Srot  [512,1492)   rotated spectrum float2 (49 x 10)
//   sigF  [1492,5972)  2 parity copies of float pairs
//   proj  [5972,16862) fp16 padded projection, 5 channels, half2 words
#define SIG_OFF  1492
#define PROJ_OFF 5972
#define SMEM_WORDS 16862
#define SMEM_BYTES (SMEM_WORDS * 4)

__global__ void __launch_bounds__(BLOCK, 3)
decoder_kernel(const float* __restrict__ angles,
               const float* __restrict__ spectrum,
               float* __restrict__ out) {
    extern __shared__ float sm[];
    float*  dS   = sm;
    float*  cpow = sm + 455;
    float*  spow = sm + 468;
    float*  cA   = sm + 481;
    float*  sA   = sm + 488;
    float*  cG   = sm + 495;
    float*  sG   = sm + 502;
    float2* Srot = (float2*)(sm + 512);
    float*  sigF = sm + SIG_OFF;
    float2* sigP = (float2*)(sm + SIG_OFF);
    unsigned int* projW = (unsigned int*)(sm + PROJ_OFF);

    const int n = blockIdx.x;
    const int tid = threadIdx.x;

    const float alpha = angles[3 * n + 0];
    const float beta  = angles[3 * n + 1];
    const float gamma = angles[3 * n + 2];

    // --- Phase A0: trig tables, zero sig copies ---
    if (tid < 7) {
        float s, c;
        sincosf((float)tid * alpha, &s, &c);
        cA[tid] = c; sA[tid] = s;
    } else if (tid < 14) {
        int m = tid - 7;
        float s, c;
        sincosf((float)m * gamma, &s, &c);
        cG[m] = c; sG[m] = s;
    } else if (tid == 14) {
        float sb, cb;
        sincosf(0.5f * beta, &sb, &cb);
        float cp = 1.0f, spw = 1.0f;
#pragma unroll
        for (int e = 0; e < 13; e++) {
            cpow[e] = cp; spow[e] = spw;
            cp *= cb; spw *= sb;
        }
    }
    for (int i = tid; i < 2 * SIG_TOT_P; i += BLOCK) sigF[i] = 0.0f;
    __syncthreads();

    // --- Phase A1: Wigner small-d matrices ---
    for (int t = tid; t < 455; t += BLOCK) {
        int l = (t >= 1) + (t >= 10) + (t >= 35) + (t >= 84) + (t >= 165) + (t >= 286);
        int n1 = 2 * l + 1;
        int loc = t - dloff(l);
        int base = slotbase(l) + loc * n1;
        float sum = 0.0f;
        for (int k = 0; k < n1; k++) {
            float cf = g_tcoef[base + k];
            int pc = (int)g_tpc[base + k];
            int ps = (int)g_tps[base + k];
            sum += cf * cpow[pc] * spow[ps];
        }
        dS[t] = sum;
    }
    __syncthreads();

    // --- Phase A2: complex Wigner-D rotate ---
    if (tid < 2 * MTOT) {
        int row = tid >> 1;
        int rbase = (tid & 1) * 5;
        int l = (row >= 1) + (row >= 4) + (row >= 9) + (row >= 16) + (row >= 25) + (row >= 36);
        int i = row - l * l;
        int mp = i - l;
        int n1 = 2 * l + 1;
        float camp = cA[mp < 0 ? -mp : mp];
        float samp = mp < 0 ? -sA[-mp] : sA[mp];
        float are[5], aim[5];
#pragma unroll
        for (int r = 0; r < 5; r++) { are[r] = 0.0f; aim[r] = 0.0f; }
        const float* drow = dS + dloff(l) + i * n1;
        for (int j = 0; j < n1; j++) {
            int m = j - l;
            float cg = cG[m < 0 ? -m : m];
            float sg = m < 0 ? -sG[-m] : sG[m];
            float cosang = camp * cg - samp * sg;
            float sinang = samp * cg + camp * sg;
            float dd = drow[j];
            float Dre = dd * cosang;
            float Dim = -dd * sinang;
            const float* sp2 = spectrum + (l * l + j) * 2 * NREP + 2 * rbase;
#pragma unroll
            for (int r = 0; r < 5; r++) {
                float sre = sp2[2 * r];
                float sim = sp2[2 * r + 1];
                are[r] += Dre * sre - Dim * sim;
                aim[r] += Dre * sim + Dim * sre;
            }
        }
#pragma unroll
        for (int r = 0; r < 5; r++)
            Srot[row * NREP + rbase + r] = make_float2(are[r], aim[r]);
    }
    __syncthreads();

    // --- Phase B: S2 inverse transform -> fp32 parity copies ---
    for (int t = tid; t < 2 * NJK; t += BLOCK) {
        int jk = t >> 1;
        int rbase = (t & 1) * 5;
        float acc[5];
#pragma unroll
        for (int r = 0; r < 5; r++) acc[r] = 0.0f;
        for (int m = 0; m < MTOT; m++) {
            float2 y = g_Yc[m * NJK + jk];
            const float2* s = Srot + m * NREP + rbase;
#pragma unroll
            for (int r = 0; r < 5; r++) {
                float2 sv = s[r];
                acc[r] += sv.x * y.x - sv.y * y.y;
            }
        }
        int j = jk / 14, k = jk % 14;
#pragma unroll
        for (int r = 0; r < 5; r++) {
            int rr = rbase + r;
            float v = acc[r];
            sigF[(rr * SIG_R_P + j * 8) * 2 + k] = v;
            if (k > 0)
                sigF[(SIG_COPY_P + rr * SIG_R_P + j * 8) * 2 + (k - 1)] = v;
        }
    }
    __syncthreads();

    // --- Phases C+D: two passes of 5 channels each ---
    float* outn = out + (size_t)n * 16384;
#pragma unroll
    for (int g = 0; g < 2; g++) {
        const int cbase = g * NGRP;

        // Phase C: bilinear grid sample -> padded fp16 proj (5 channels)
        for (int task = tid; task < 66 * PROJ_ROW_W; task += BLOCK) {
            int srow = task / PROJ_ROW_W;
            int w = task - srow * PROJ_ROW_W;
            unsigned int pofs = (unsigned int)(srow * PROJ_ROW_W + w);
            if (srow == 0 || srow == 65) {
#pragma unroll
                for (int cl = 0; cl < NGRP; cl++) projW[cl * PROJ_C_W + pofs] = 0u;
                continue;
            }
            int row = srow - 1;
            int e = row * 66 + 2 * w;
            float4 wA = g_tpw[e];
            float4 wB = g_tpw[e + 1];
            int2 oA = g_tpo[e];
            int2 oB = g_tpo[e + 1];
#pragma unroll
            for (int cl = 0; cl < NGRP; cl++) {
                int rofs = (cbase + cl) * SIG_R_P;
                float2 a0 = sigP[oA.x + rofs];
                float2 a1 = sigP[oA.y + rofs];
                float v0 = wA.x * a0.x + wA.y * a0.y + wA.z * a1.x + wA.w * a1.y;
                float2 b0 = sigP[oB.x + rofs];
                float2 b1 = sigP[oB.y + rofs];
                float v1 = wB.x * b0.x + wB.y * b0.y + wB.z * b1.x + wB.w * b1.y;
                __half2 pv = __floats2half2_rn(v0, v1);
                projW[cl * PROJ_C_W + pofs] = *(unsigned int*)&pv;
            }
        }
        __syncthreads();

        // Phase D partial: tile-sequential, merge into global out
#pragma unroll
        for (int t4 = 0; t4 < 4; t4++) {
            int t = tid + t4 * BLOCK;
            int ty = t >> 5;
            int tx = t & 31;
            float acc[4][4];
            float binit = (g == 0) ? c_bt[0] : 0.0f;
#pragma unroll
            for (int dy = 0; dy < 4; dy++)
#pragma unroll
                for (int dx = 0; dx < 4; dx++) acc[dy][dx] = binit;

#pragma unroll
            for (int cl = 0; cl < NGRP; cl++) {
                int c = cbase + cl;
                float P[4][4];
#pragma unroll
                for (int yy = 0; yy < 4; yy++) {
                    unsigned int base = (unsigned int)((cl * 66 + 2 * ty + yy) * PROJ_ROW_W + tx);
                    float2 ab = __half22float2(*(__half2*)&projW[base]);
                    float2 cd = __half22float2(*(__half2*)&projW[base + 1]);
                    P[yy][0] = ab.x; P[yy][1] = ab.y;
                    P[yy][2] = cd.x; P[yy][3] = cd.y;
                }
#pragma unroll
                for (int dy = 0; dy < 4; dy++) {
                    int pl = dy >> 1;
                    int py = dy & 1;
                    int ry0 = py ? pl + 2 : pl + 1;
                    int ry1 = py ? pl + 1 : pl;
                    int kya = py ? 0 : 1;
                    int kyb = py ? 2 : 3;
#pragma unroll
                    for (int dx = 0; dx < 4; dx++) {
                        int ql = dx >> 1;
                        int px = dx & 1;
                        int rx0 = px ? ql + 2 : ql + 1;
                        int rx1 = px ? ql + 1 : ql;
                        int kxa = px ? 0 : 1;
                        int kxb = px ? 2 : 3;
                        acc[dy][dx] += P[ry0][rx0] * c_wt[c * 16 + kya * 4 + kxa]
                                     + P[ry0][rx1] * c_wt[c * 16 + kya * 4 + kxb]
                                     + P[ry1][rx0] * c_wt[c * 16 + kyb * 4 + kxa]
                                     + P[ry1][rx1] * c_wt[c * 16 + kyb * 4 + kxb];
                    }
                }
            }
#pragma unroll
            for (int dy = 0; dy < 4; dy++) {
                float4* dst = reinterpret_cast<float4*>(outn + (size_t)(4 * ty + dy) * 128 + 4 * tx);
                float4 v;
                if (g == 0) {
                    v = make_float4(acc[dy][0], acc[dy][1], acc[dy][2], acc[dy][3]);
                } else {
                    float4 prev = *dst;
                    v = make_float4(prev.x + acc[dy][0], prev.y + acc[dy][1],
                                    prev.z + acc[dy][2], prev.w + acc[dy][3]);
                }
                *dst = v;
            }
        }
        if (g == 0) __syncthreads();   // protect proj before pass-1 overwrite
    }
}

// ---------------------------------------------------------------------------
extern "C" void kernel_launch(void* const* d_in, const int* in_sizes, int n_in,
                              void* d_out, int out_size) {
    const float* angles   = (const float*)d_in[0];
    const float* spectrum = (const float*)d_in[1];
    const float* wt       = (const float*)d_in[2];
    const float* bt       = (const float*)d_in[3];
    float* out = (float*)d_out;

    cudaFuncSetAttribute(decoder_kernel,
                         cudaFuncAttributeMaxDynamicSharedMemorySize, SMEM_BYTES);

    cudaMemcpyToSymbolAsync(c_wt, wt, 160 * sizeof(float), 0,
                            cudaMemcpyDeviceToDevice);
    cudaMemcpyToSymbolAsync(c_bt, bt, sizeof(float), 0,
                            cudaMemcpyDeviceToDevice);

    // 64 blocks x 256 = 16384 threads: covers taps up to 8192+4224=12416.
    setup_kernel<<<64, 256>>>();
    decoder_kernel<<<NPOSE, BLOCK, SMEM_BYTES>>>(angles, spectrum, out);
}

// round 10
// speedup vs baseline: 1.8651x; 1.0663x over previous
#include <cuda_runtime.h>
#include <cuda_fp16.h>
#include <math.h>

// ---------------------------------------------------------------------------
// ProjectionDecoder: Wigner rotate -> S2 ifft -> grid_sample -> convtranspose
// angles (2048,3) f32; spectrum (49,10,2) f32; wt (10,1,4,4) f32; bt (1) f32
// out (2048,1,128,128) f32
//
// R10: sig stored as fp32 QUADS (2x2 bilinear footprint in one float4) so
// phase C is one LDS.128 per (col,channel); phase D runs in 4 row-group
// passes (proj 18 rows x 10 ch resident, no global RMW); phase B handles
// 2 grid points per thread (Srot loads halved). 3 blocks/SM, 68.1 KB smem.
// ---------------------------------------------------------------------------

#define NPOSE 2048
#define MTOT  49
#define NREP  10
#define NJK   196     // 14*14
#define NSLOT 4753    // sum (2l+1)^3, l=0..6
#define BLOCK 256

// sigQ: [xp(2)][r(10)][yq(15)][hh(8)] float4 quads
//   quad(xp,r,yq,hh) = {s[yq-1][c0], s[yq-1][c0+1], s[yq][c0], s[yq][c0+1]},
//   c0 = 2*hh+xp; rows -1,14 and col 14 slots stay zero.
#define SIGQ_XP_Q   1200       // 10*15*8 quads per x-parity
#define SIGQ_R_Q    120        // 15*8
#define SIGQ_TOT_Q  2400
#define SIGQ_TOT_F  9600       // floats

// proj (per row-group pass): [c(10)][srow(18)][33 words] of half2
#define PROJ_ROW_W  33
#define PROJ_C_W    (18 * PROJ_ROW_W)    // 594
#define PROJ_TOT_W  (NREP * PROJ_C_W)    // 5940

#define NTAP  (64 * 66)   // tap entries indexed [projrow][stored h]

__device__ float       g_tcoef[NSLOT];
__device__ signed char g_tpc[NSLOT];
__device__ signed char g_tps[NSLOT];
__device__ float2      g_Yc[MTOT * NJK];   // {Yre, Yim}
__device__ float4      g_tqw[NTAP];        // quad weights (w00,w01,w10,w11)
__device__ int         g_tqo[NTAP];        // quad index (excl. r term)

__constant__ float  c_wt[160];   // deconv weights (10 x 16)
__constant__ float  c_bt[1];     // bias
__constant__ double c_fact[13] = {
    1.0, 1.0, 2.0, 6.0, 24.0, 120.0, 720.0, 5040.0,
    40320.0, 362880.0, 3628800.0, 39916800.0, 479001600.0 };

__device__ __forceinline__ int slotbase(int l) { return l * l * (2 * l * l - 1); }
__device__ __forceinline__ int dloff(int l) { return l * (4 * l * l - 1) / 3; }

#define PI_F 3.14159265358979323846f

// ---------------------------------------------------------------------------
// Setup kernel: input-independent tables.
// ---------------------------------------------------------------------------
__global__ void setup_kernel() {
    int g = blockIdx.x * blockDim.x + threadIdx.x;

    if (g < NSLOT) {
        int l = (g >= 1) + (g >= 28) + (g >= 153) + (g >= 496) + (g >= 1225) + (g >= 2556);
        int n1 = 2 * l + 1;
        int rem = g - slotbase(l);
        int i = rem / (n1 * n1);
        int j = (rem / n1) % n1;
        int k = rem % n1;
        int mp = i - l, m = j - l;
        int kmin = max(0, m - mp);
        int kmax = min(l + m, l - mp);
        float coef = 0.0f;
        int pc = 0, ps = 0;
        if (k >= kmin && k <= kmax) {
            double pref = sqrt(c_fact[l + mp] * c_fact[l - mp] * c_fact[l + m] * c_fact[l - m]);
            double c = pref / (c_fact[l + m - k] * c_fact[k] * c_fact[l - mp - k] * c_fact[mp - m + k]);
            if ((mp - m + k) & 1) c = -c;
            coef = (float)c;
            pc = 2 * l + m - mp - 2 * k;
            ps = mp - m + 2 * k;
        }
        g_tcoef[g] = coef;
        g_tpc[g] = (signed char)pc;
        g_tps[g] = (signed char)ps;
    } else if (g >= 5120 && g < 5120 + NJK) {
        // Spherical harmonic table Y (49, 14, 14)
        int jk = g - 5120;
        int j = jk / 14, k = jk % 14;
        float beta = PI_F * (2.0f * j + 1.0f) / 28.0f;
        float x, sx;
        sincosf(beta, &sx, &x);
        float P[7][7];
#pragma unroll
        for (int a = 0; a < 7; a++)
#pragma unroll
            for (int b = 0; b < 7; b++) P[a][b] = 0.0f;
        P[0][0] = 1.0f;
        for (int m = 1; m <= 6; m++) P[m][m] = -(2.0f * m - 1.0f) * sx * P[m - 1][m - 1];
        for (int m = 0; m <= 6; m++) {
            if (m + 1 <= 6) P[m + 1][m] = (2.0f * m + 1.0f) * x * P[m][m];
            for (int l = m + 2; l <= 6; l++)
                P[l][m] = ((2.0f * l - 1.0f) * x * P[l - 1][m] - (l + m - 1.0f) * P[l - 2][m]) / (float)(l - m);
        }
        float alk = 2.0f * PI_F * (float)k / 14.0f;
        for (int l = 0; l <= 6; l++) {
            for (int m = 0; m <= l; m++) {
                float Nn = sqrtf((2.0f * l + 1.0f) / (4.0f * PI_F)
                                 * (float)(c_fact[l - m] / c_fact[l + m]));
                float pr = Nn * P[l][m];
                float sm_, cm_;
                sincosf((float)m * alk, &sm_, &cm_);
                float yre = pr * cm_;
                float yim = pr * sm_;
                g_Yc[(l * l + l + m) * NJK + jk] = make_float2(yre, yim);
                if (m > 0) {
                    float sgn = (m & 1) ? -1.0f : 1.0f;
                    g_Yc[(l * l + l - m) * NJK + jk] = make_float2(sgn * yre, -sgn * yim);
                }
            }
        }
    } else if (g >= 8192 && g < 8192 + NTAP) {
        // Quad tap entry for (proj row, stored h). col = h - 1.
        int idx = g - 8192;
        int row = idx / 66;
        int h = idx % 66;
        int col = h - 1;
        float4 w4 = make_float4(0.f, 0.f, 0.f, 0.f);
        int off = 0;
        if (col >= 0 && col < 64) {
            float step = 1.6f / 63.0f;
            float yv = -0.8f + row * step;
            float xv = -0.8f + col * step;
            float rho = sqrtf(xv * xv + yv * yv);
            float th = asinf(fminf(rho, 1.0f));
            float ph = atan2f(yv, xv);
            float gx = ph / PI_F;
            float gy = 2.0f * th / PI_F - 1.0f;
            float gpx = (gx + 1.0f) * 7.0f - 0.5f;
            float gpy = (gy + 1.0f) * 7.0f - 0.5f;
            float x0f = floorf(gpx), y0f = floorf(gpy);
            int x0 = (int)x0f, y0 = (int)y0f;   // x0,y0 in [-1,13]
            float fx = gpx - x0f, fy = gpy - y0f;
            float wx0 = 1.0f - fx, wx1 = fx;
            float wy0 = 1.0f - fy, wy1 = fy;
            float vy0 = (y0 >= 0) ? 1.0f : 0.0f;        // y0 <= 13 always
            float vy1 = (y0 + 1 <= 13) ? 1.0f : 0.0f;
            int xp, hh;
            if (x0 >= 0) {
                float vx1 = (x0 + 1 <= 13) ? 1.0f : 0.0f;
                xp = x0 & 1;
                hh = x0 >> 1;
                w4 = make_float4(wx0 * wy0 * vy0, wx1 * wy0 * vx1 * vy0,
                                 wx0 * wy1 * vy1, wx1 * wy1 * vx1 * vy1);
            } else {  // x0 == -1: only tap at col 0 with weight wx1
                xp = 0; hh = 0;
                w4 = make_float4(wx1 * wy0 * vy0, 0.0f,
                                 wx1 * wy1 * vy1, 0.0f);
            }
            off = xp * SIGQ_XP_Q + (y0 + 1) * 8 + hh;
        }
        g_tqw[idx] = w4;
        g_tqo[idx] = off;
    }
}

// ---------------------------------------------------------------------------
// Main fused kernel: one block (256 threads) per pose n, 3 blocks/SM.
// smem word layout (4B words):
//   dS [0,455)  cpow [455,468)  spow [468,481)
//   cA [481,488) sA [488,495) cG [495,502) sG [502,509)
//   Srot  [512,1492)    rotated spectrum float2 (49 x 10)
//   sigQ  [1492,11092)  fp32 quads (float4-aligned: 1492*4 = 5968 % 16 == 0)
//   proj  [11092,17032) fp16 row-group projection, half2 words
#define SIGQ_OFF  1492
#define PROJ_OFF  11092
#define SMEM_WORDS 17032
#define SMEM_BYTES (SMEM_WORDS * 4)

__global__ void __launch_bounds__(BLOCK, 3)
decoder_kernel(const float* __restrict__ angles,
               const float* __restrict__ spectrum,
               float* __restrict__ out) {
    extern __shared__ float sm[];
    float*  dS   = sm;
    float*  cpow = sm + 455;
    float*  spow = sm + 468;
    float*  cA   = sm + 481;
    float*  sA   = sm + 488;
    float*  cG   = sm + 495;
    float*  sG   = sm + 502;
    float2* Srot = (float2*)(sm + 512);
    float*  sigQf = sm + SIGQ_OFF;
    float4* sigQ4 = (float4*)(sm + SIGQ_OFF);
    unsigned int* projW = (unsigned int*)(sm + PROJ_OFF);

    const int n = blockIdx.x;
    const int tid = threadIdx.x;

    const float alpha = angles[3 * n + 0];
    const float beta  = angles[3 * n + 1];
    const float gamma = angles[3 * n + 2];

    // --- Phase A0: trig tables, zero sig quads ---
    if (tid < 7) {
        float s, c;
        sincosf((float)tid * alpha, &s, &c);
        cA[tid] = c; sA[tid] = s;
    } else if (tid < 14) {
        int m = tid - 7;
        float s, c;
        sincosf((float)m * gamma, &s, &c);
        cG[m] = c; sG[m] = s;
    } else if (tid == 14) {
        float sb, cb;
        sincosf(0.5f * beta, &sb, &cb);
        float cp = 1.0f, spw = 1.0f;
#pragma unroll
        for (int e = 0; e < 13; e++) {
            cpow[e] = cp; spow[e] = spw;
            cp *= cb; spw *= sb;
        }
    }
    for (int i = tid; i < SIGQ_TOT_F; i += BLOCK) sigQf[i] = 0.0f;
    __syncthreads();

    // --- Phase A1: Wigner small-d matrices ---
    for (int t = tid; t < 455; t += BLOCK) {
        int l = (t >= 1) + (t >= 10) + (t >= 35) + (t >= 84) + (t >= 165) + (t >= 286);
        int n1 = 2 * l + 1;
        int loc = t - dloff(l);
        int base = slotbase(l) + loc * n1;
        float sum = 0.0f;
        for (int k = 0; k < n1; k++) {
            float cf = g_tcoef[base + k];
            int pc = (int)g_tpc[base + k];
            int ps = (int)g_tps[base + k];
            sum += cf * cpow[pc] * spow[ps];
        }
        dS[t] = sum;
    }
    __syncthreads();

    // --- Phase A2: complex Wigner-D rotate ---
    if (tid < 2 * MTOT) {
        int row = tid >> 1;
        int rbase = (tid & 1) * 5;
        int l = (row >= 1) + (row >= 4) + (row >= 9) + (row >= 16) + (row >= 25) + (row >= 36);
        int i = row - l * l;
        int mp = i - l;
        int n1 = 2 * l + 1;
        float camp = cA[mp < 0 ? -mp : mp];
        float samp = mp < 0 ? -sA[-mp] : sA[mp];
        float are[5], aim[5];
#pragma unroll
        for (int r = 0; r < 5; r++) { are[r] = 0.0f; aim[r] = 0.0f; }
        const float* drow = dS + dloff(l) + i * n1;
        for (int j = 0; j < n1; j++) {
            int m = j - l;
            float cg = cG[m < 0 ? -m : m];
            float sg = m < 0 ? -sG[-m] : sG[m];
            float cosang = camp * cg - samp * sg;
            float sinang = samp * cg + camp * sg;
            float dd = drow[j];
            float Dre = dd * cosang;
            float Dim = -dd * sinang;
            const float* sp2 = spectrum + (l * l + j) * 2 * NREP + 2 * rbase;
#pragma unroll
            for (int r = 0; r < 5; r++) {
                float sre = sp2[2 * r];
                float sim = sp2[2 * r + 1];
                are[r] += Dre * sre - Dim * sim;
                aim[r] += Dre * sim + Dim * sre;
            }
        }
#pragma unroll
        for (int r = 0; r < 5; r++)
            Srot[row * NREP + rbase + r] = make_float2(are[r], aim[r]);
    }
    __syncthreads();

    // --- Phase B: S2 inverse transform -> fp32 quad copies ---
    // 196 threads: each handles 2 grid points (jk, jk+98) x 5 reps, so each
    // Srot row is loaded once per 2 points.
    if (tid < 196) {
        int jk0 = tid >> 1;
        int jk1 = jk0 + 98;
        int rbase = (tid & 1) * 5;
        float acc0[5], acc1[5];
#pragma unroll
        for (int r = 0; r < 5; r++) { acc0[r] = 0.0f; acc1[r] = 0.0f; }
        for (int m = 0; m < MTOT; m++) {
            float2 y0v = g_Yc[m * NJK + jk0];
            float2 y1v = g_Yc[m * NJK + jk1];
            const float2* s = Srot + m * NREP + rbase;
#pragma unroll
            for (int r = 0; r < 5; r++) {
                float2 sv = s[r];
                acc0[r] += sv.x * y0v.x - sv.y * y0v.y;
                acc1[r] += sv.x * y1v.x - sv.y * y1v.y;
            }
        }
#pragma unroll
        for (int half = 0; half < 2; half++) {
            int jk = half ? jk1 : jk0;
            int j = jk / 14, k = jk % 14;
            int kh = k >> 1;
#pragma unroll
            for (int r = 0; r < 5; r++) {
                int rr = rbase + r;
                float v = half ? acc1[r] : acc0[r];
                int rq = rr * SIGQ_R_Q;
                // xp0: value at (row j, col k)
                sigQf[((rq + (j + 1) * 8 + kh) << 2) + (k & 1)] = v;
                sigQf[((rq + j * 8 + kh) << 2) + 2 + (k & 1)] = v;
                // xp1 copy
                if (k & 1) {
                    int b = SIGQ_XP_Q + rq;
                    sigQf[((b + (j + 1) * 8 + kh) << 2) + 0] = v;
                    sigQf[((b + j * 8 + kh) << 2) + 2] = v;
                } else if (k >= 2) {
                    int b = SIGQ_XP_Q + rq;
                    int hh = kh - 1;
                    sigQf[((b + (j + 1) * 8 + hh) << 2) + 1] = v;
                    sigQf[((b + j * 8 + hh) << 2) + 3] = v;
                }
            }
        }
    }
    __syncthreads();

    // --- Phases C+D: four row-group passes (out rows 32g..32g+32) ---
    float* outn = out + (size_t)n * 16384;
    const float bias = c_bt[0];
#pragma unroll
    for (int g = 0; g < 4; g++) {
        // Phase C: proj rows [16g-1, 16g+17) -> fp16 proj buffer (10 ch)
        for (int task = tid; task < 18 * PROJ_ROW_W; task += BLOCK) {
            int srow = task / PROJ_ROW_W;
            int w = task - srow * PROJ_ROW_W;
            int grow = 16 * g - 1 + srow;
            unsigned int pofs = (unsigned int)(srow * PROJ_ROW_W + w);
            if ((unsigned)grow >= 64u) {
#pragma unroll
                for (int c = 0; c < NREP; c++) projW[c * PROJ_C_W + pofs] = 0u;
                continue;
            }
            int e = grow * 66 + 2 * w;
            float4 wA = g_tqw[e];
            float4 wB = g_tqw[e + 1];
            int oA = g_tqo[e];
            int oB = g_tqo[e + 1];
#pragma unroll
            for (int c = 0; c < NREP; c++) {
                int rq = c * SIGQ_R_Q;
                float4 qa = sigQ4[oA + rq];
                float4 qb = sigQ4[oB + rq];
                float v0 = wA.x * qa.x + wA.y * qa.y + wA.z * qa.z + wA.w * qa.w;
                float v1 = wB.x * qb.x + wB.y * qb.y + wB.z * qb.z + wB.w * qb.w;
                __half2 pv = __floats2half2_rn(v0, v1);
                projW[c * PROJ_C_W + pofs] = *(unsigned int*)&pv;
            }
        }
        __syncthreads();

        // Phase D: one 4x4 output tile per thread (out rows 32g..32g+32)
        {
            int tyl = tid >> 5;         // 0..7
            int tx = tid & 31;
            float acc[4][4];
#pragma unroll
            for (int dy = 0; dy < 4; dy++)
#pragma unroll
                for (int dx = 0; dx < 4; dx++) acc[dy][dx] = bias;

#pragma unroll
            for (int c = 0; c < NREP; c++) {
                float P[4][4];
#pragma unroll
                for (int yy = 0; yy < 4; yy++) {
                    unsigned int base = (unsigned int)((c * 18 + 2 * tyl + yy) * PROJ_ROW_W + tx);
                    float2 ab = __half22float2(*(__half2*)&projW[base]);
                    float2 cd = __half22float2(*(__half2*)&projW[base + 1]);
                    P[yy][0] = ab.x; P[yy][1] = ab.y;
                    P[yy][2] = cd.x; P[yy][3] = cd.y;
                }
#pragma unroll
                for (int dy = 0; dy < 4; dy++) {
                    int pl = dy >> 1;
                    int py = dy & 1;
                    int ry0 = py ? pl + 2 : pl + 1;
                    int ry1 = py ? pl + 1 : pl;
                    int kya = py ? 0 : 1;
                    int kyb = py ? 2 : 3;
#pragma unroll
                    for (int dx = 0; dx < 4; dx++) {
                        int ql = dx >> 1;
                        int px = dx & 1;
                        int rx0 = px ? ql + 2 : ql + 1;
                        int rx1 = px ? ql + 1 : ql;
                        int kxa = px ? 0 : 1;
                        int kxb = px ? 2 : 3;
                        acc[dy][dx] += P[ry0][rx0] * c_wt[c * 16 + kya * 4 + kxa]
                                     + P[ry0][rx1] * c_wt[c * 16 + kya * 4 + kxb]
                                     + P[ry1][rx0] * c_wt[c * 16 + kyb * 4 + kxa]
                                     + P[ry1][rx1] * c_wt[c * 16 + kyb * 4 + kxb];
                    }
                }
            }
            int orow0 = 32 * g + 4 * tyl;
#pragma unroll
            for (int dy = 0; dy < 4; dy++) {
                float4 v = make_float4(acc[dy][0], acc[dy][1], acc[dy][2], acc[dy][3]);
                *reinterpret_cast<float4*>(outn + (size_t)(orow0 + dy) * 128 + 4 * tx) = v;
            }
        }
        if (g < 3) __syncthreads();   // protect proj before next pass's C
    }
}

// ---------------------------------------------------------------------------
extern "C" void kernel_launch(void* const* d_in, const int* in_sizes, int n_in,
                              void* d_out, int out_size) {
    const float* angles   = (const float*)d_in[0];
    const float* spectrum = (const float*)d_in[1];
    const float* wt       = (const float*)d_in[2];
    const float* bt       = (const float*)d_in[3];
    float* out = (float*)d_out;

    cudaFuncSetAttribute(decoder_kernel,
                         cudaFuncAttributeMaxDynamicSharedMemorySize, SMEM_BYTES);

    cudaMemcpyToSymbolAsync(c_wt, wt, 160 * sizeof(float), 0,
                            cudaMemcpyDeviceToDevice);
    cudaMemcpyToSymbolAsync(c_bt, bt, sizeof(float), 0,
                            cudaMemcpyDeviceToDevice);

    // 64 blocks x 256 = 16384 threads: covers taps up to 8192+4224=12416.
    setup_kernel<<<64, 256>>>();
    decoder_kernel<<<NPOSE, BLOCK, SMEM_BYTES>>>(angles, spectrum, out);
}

// round 11
// speedup vs baseline: 2.1109x; 1.1318x over previous
#include <cuda_runtime.h>
#include <cuda_fp16.h>
#include <math.h>

// ---------------------------------------------------------------------------
// ProjectionDecoder: Wigner rotate -> S2 ifft -> grid_sample -> convtranspose
// angles (2048,3) f32; spectrum (49,10,2) f32; wt (10,1,4,4) f32; bt (1) f32
// out (2048,1,128,128) f32
//
// R11: sig quads in fp16 (8B per 2x2 bilinear footprint -> LDS.64 gathers,
// phase-C smem bytes halved); 2 C/D row-group passes (34-row proj window);
// Y table packed float4 (1 LDG.128 per m in phase B). 3 blocks/SM, ~70 KB.
// ---------------------------------------------------------------------------

#define NPOSE 2048
#define MTOT  49
#define NREP  10
#define NJK   196     // 14*14
#define NSLOT 4753    // sum (2l+1)^3, l=0..6
#define BLOCK 256

// sigQ (fp16): [xp(2)][r(10)][yq(15)][hh(8)] quads; each quad = 2 words
//   quad halves [4q..4q+4) = {s[yq-1][c0], s[yq-1][c0+1], s[yq][c0], s[yq][c0+1]}
//   c0 = 2*hh+xp; rows -1,14 and col 14 slots stay zero.
#define SIGQ_XP_Q   1200       // quads per x-parity
#define SIGQ_R_Q    120        // 15*8
#define SIGQ_TOT_Q  2400
#define SIGQ_TOT_W  4800       // 32-bit words

// proj (per pass): [c(10)][srow(34)][33 words] of half2; word w = cols (2w-1,2w)
#define PROJ_ROW_W  33
#define PROJ_C_W    (34 * PROJ_ROW_W)    // 1122
#define PROJ_TOT_W  (NREP * PROJ_C_W)    // 11220

#define NTAP  (64 * 66)   // tap entries indexed [projrow][stored h]

__device__ float       g_tcoef[NSLOT];
__device__ signed char g_tpc[NSLOT];
__device__ signed char g_tps[NSLOT];
__device__ float4      g_Yc4[MTOT * 98];   // {Yre(jk),Yim(jk),Yre(jk+98),Yim(jk+98)}
__device__ float4      g_tqw[NTAP];        // quad weights (w00,w01,w10,w11)
__device__ int         g_tqo[NTAP];        // quad index (excl. r term)

__constant__ float  c_wt[160];   // deconv weights (10 x 16)
__constant__ float  c_bt[1];     // bias
__constant__ double c_fact[13] = {
    1.0, 1.0, 2.0, 6.0, 24.0, 120.0, 720.0, 5040.0,
    40320.0, 362880.0, 3628800.0, 39916800.0, 479001600.0 };

__device__ __forceinline__ int slotbase(int l) { return l * l * (2 * l * l - 1); }
__device__ __forceinline__ int dloff(int l) { return l * (4 * l * l - 1) / 3; }

#define PI_F 3.14159265358979323846f

// ---------------------------------------------------------------------------
// Setup kernel: input-independent tables.
// ---------------------------------------------------------------------------
__global__ void setup_kernel() {
    int g = blockIdx.x * blockDim.x + threadIdx.x;

    if (g < NSLOT) {
        int l = (g >= 1) + (g >= 28) + (g >= 153) + (g >= 496) + (g >= 1225) + (g >= 2556);
        int n1 = 2 * l + 1;
        int rem = g - slotbase(l);
        int i = rem / (n1 * n1);
        int j = (rem / n1) % n1;
        int k = rem % n1;
        int mp = i - l, m = j - l;
        int kmin = max(0, m - mp);
        int kmax = min(l + m, l - mp);
        float coef = 0.0f;
        int pc = 0, ps = 0;
        if (k >= kmin && k <= kmax) {
            double pref = sqrt(c_fact[l + mp] * c_fact[l - mp] * c_fact[l + m] * c_fact[l - m]);
            double c = pref / (c_fact[l + m - k] * c_fact[k] * c_fact[l - mp - k] * c_fact[mp - m + k]);
            if ((mp - m + k) & 1) c = -c;
            coef = (float)c;
            pc = 2 * l + m - mp - 2 * k;
            ps = mp - m + 2 * k;
        }
        g_tcoef[g] = coef;
        g_tpc[g] = (signed char)pc;
        g_tps[g] = (signed char)ps;
    } else if (g >= 5120 && g < 5120 + NJK) {
        // Spherical harmonic table Y (49, 14, 14), packed into float4 pairs
        int jk = g - 5120;
        int j = jk / 14, k = jk % 14;
        int jkh = (jk < 98) ? jk : jk - 98;
        int comp = (jk < 98) ? 0 : 2;
        float* Yf = (float*)g_Yc4;
        float beta = PI_F * (2.0f * j + 1.0f) / 28.0f;
        float x, sx;
        sincosf(beta, &sx, &x);
        float P[7][7];
#pragma unroll
        for (int a = 0; a < 7; a++)
#pragma unroll
            for (int b = 0; b < 7; b++) P[a][b] = 0.0f;
        P[0][0] = 1.0f;
        for (int m = 1; m <= 6; m++) P[m][m] = -(2.0f * m - 1.0f) * sx * P[m - 1][m - 1];
        for (int m = 0; m <= 6; m++) {
            if (m + 1 <= 6) P[m + 1][m] = (2.0f * m + 1.0f) * x * P[m][m];
            for (int l = m + 2; l <= 6; l++)
                P[l][m] = ((2.0f * l - 1.0f) * x * P[l - 1][m] - (l + m - 1.0f) * P[l - 2][m]) / (float)(l - m);
        }
        float alk = 2.0f * PI_F * (float)k / 14.0f;
        for (int l = 0; l <= 6; l++) {
            for (int m = 0; m <= l; m++) {
                float Nn = sqrtf((2.0f * l + 1.0f) / (4.0f * PI_F)
                                 * (float)(c_fact[l - m] / c_fact[l + m]));
                float pr = Nn * P[l][m];
                float sm_, cm_;
                sincosf((float)m * alk, &sm_, &cm_);
                float yre = pr * cm_;
                float yim = pr * sm_;
                int b0 = ((l * l + l + m) * 98 + jkh) * 4 + comp;
                Yf[b0] = yre;
                Yf[b0 + 1] = yim;
                if (m > 0) {
                    float sgn = (m & 1) ? -1.0f : 1.0f;
                    int b1 = ((l * l + l - m) * 98 + jkh) * 4 + comp;
                    Yf[b1] = sgn * yre;
                    Yf[b1 + 1] = -sgn * yim;
                }
            }
        }
    } else if (g >= 8192 && g < 8192 + NTAP) {
        // Quad tap entry for (proj row, stored h). col = h - 1.
        int idx = g - 8192;
        int row = idx / 66;
        int h = idx % 66;
        int col = h - 1;
        float4 w4 = make_float4(0.f, 0.f, 0.f, 0.f);
        int off = 0;
        if (col >= 0 && col < 64) {
            float step = 1.6f / 63.0f;
            float yv = -0.8f + row * step;
            float xv = -0.8f + col * step;
            float rho = sqrtf(xv * xv + yv * yv);
            float th = asinf(fminf(rho, 1.0f));
            float ph = atan2f(yv, xv);
            float gx = ph / PI_F;
            float gy = 2.0f * th / PI_F - 1.0f;
            float gpx = (gx + 1.0f) * 7.0f - 0.5f;
            float gpy = (gy + 1.0f) * 7.0f - 0.5f;
            float x0f = floorf(gpx), y0f = floorf(gpy);
            int x0 = (int)x0f, y0 = (int)y0f;   // x0,y0 in [-1,13]
            float fx = gpx - x0f, fy = gpy - y0f;
            float wx0 = 1.0f - fx, wx1 = fx;
            float wy0 = 1.0f - fy, wy1 = fy;
            float vy0 = (y0 >= 0) ? 1.0f : 0.0f;
            float vy1 = (y0 + 1 <= 13) ? 1.0f : 0.0f;
            int xp, hh;
            if (x0 >= 0) {
                float vx1 = (x0 + 1 <= 13) ? 1.0f : 0.0f;
                xp = x0 & 1;
                hh = x0 >> 1;
                w4 = make_float4(wx0 * wy0 * vy0, wx1 * wy0 * vx1 * vy0,
                                 wx0 * wy1 * vy1, wx1 * wy1 * vx1 * vy1);
            } else {  // x0 == -1: only tap at col 0 with weight wx1
                xp = 0; hh = 0;
                w4 = make_float4(wx1 * wy0 * vy0, 0.0f,
                                 wx1 * wy1 * vy1, 0.0f);
            }
            off = xp * SIGQ_XP_Q + (y0 + 1) * 8 + hh;
        }
        g_tqw[idx] = w4;
        g_tqo[idx] = off;
    }
}

// ---------------------------------------------------------------------------
// Main fused kernel: one block (256 threads) per pose n, 3 blocks/SM.
// smem word layout (4B words):
//   dS [0,455)  cpow [455,468)  spow [468,481)
//   cA [481,488) sA [488,495) cG [495,502) sG [502,509)
//   Srot  [512,1492)    rotated spectrum float2 (49 x 10)
//   sigQ  [1492,6292)   fp16 quads, uint2 each (8B aligned: 1492 even)
//   proj  [6292,17512)  fp16 row-group projection (34 rows x 10 ch)
#define SIGQ_OFF  1492
#define PROJ_OFF  6292
#define SMEM_WORDS 17512
#define SMEM_BYTES (SMEM_WORDS * 4)

__global__ void __launch_bounds__(BLOCK, 3)
decoder_kernel(const float* __restrict__ angles,
               const float* __restrict__ spectrum,
               float* __restrict__ out) {
    extern __shared__ float sm[];
    float*  dS   = sm;
    float*  cpow = sm + 455;
    float*  spow = sm + 468;
    float*  cA   = sm + 481;
    float*  sA   = sm + 488;
    float*  cG   = sm + 495;
    float*  sG   = sm + 502;
    float2* Srot = (float2*)(sm + 512);
    unsigned int* sigQW = (unsigned int*)(sm + SIGQ_OFF);
    __half* sigH = (__half*)(sm + SIGQ_OFF);
    const uint2* sigQ2 = (const uint2*)(sm + SIGQ_OFF);
    unsigned int* projW = (unsigned int*)(sm + PROJ_OFF);

    const int n = blockIdx.x;
    const int tid = threadIdx.x;

    const float alpha = angles[3 * n + 0];
    const float beta  = angles[3 * n + 1];
    const float gamma = angles[3 * n + 2];

    // --- Phase A0: trig tables, zero sig quads ---
    if (tid < 7) {
        float s, c;
        sincosf((float)tid * alpha, &s, &c);
        cA[tid] = c; sA[tid] = s;
    } else if (tid < 14) {
        int m = tid - 7;
        float s, c;
        sincosf((float)m * gamma, &s, &c);
        cG[m] = c; sG[m] = s;
    } else if (tid == 14) {
        float sb, cb;
        sincosf(0.5f * beta, &sb, &cb);
        float cp = 1.0f, spw = 1.0f;
#pragma unroll
        for (int e = 0; e < 13; e++) {
            cpow[e] = cp; spow[e] = spw;
            cp *= cb; spw *= sb;
        }
    }
    for (int i = tid; i < SIGQ_TOT_W; i += BLOCK) sigQW[i] = 0u;
    __syncthreads();

    // --- Phase A1: Wigner small-d matrices ---
    for (int t = tid; t < 455; t += BLOCK) {
        int l = (t >= 1) + (t >= 10) + (t >= 35) + (t >= 84) + (t >= 165) + (t >= 286);
        int n1 = 2 * l + 1;
        int loc = t - dloff(l);
        int base = slotbase(l) + loc * n1;
        float sum = 0.0f;
        for (int k = 0; k < n1; k++) {
            float cf = g_tcoef[base + k];
            int pc = (int)g_tpc[base + k];
            int ps = (int)g_tps[base + k];
            sum += cf * cpow[pc] * spow[ps];
        }
        dS[t] = sum;
    }
    __syncthreads();

    // --- Phase A2: complex Wigner-D rotate ---
    if (tid < 2 * MTOT) {
        int row = tid >> 1;
        int rbase = (tid & 1) * 5;
        int l = (row >= 1) + (row >= 4) + (row >= 9) + (row >= 16) + (row >= 25) + (row >= 36);
        int i = row - l * l;
        int mp = i - l;
        int n1 = 2 * l + 1;
        float camp = cA[mp < 0 ? -mp : mp];
        float samp = mp < 0 ? -sA[-mp] : sA[mp];
        float are[5], aim[5];
#pragma unroll
        for (int r = 0; r < 5; r++) { are[r] = 0.0f; aim[r] = 0.0f; }
        const float* drow = dS + dloff(l) + i * n1;
        for (int j = 0; j < n1; j++) {
            int m = j - l;
            float cg = cG[m < 0 ? -m : m];
            float sg = m < 0 ? -sG[-m] : sG[m];
            float cosang = camp * cg - samp * sg;
            float sinang = samp * cg + camp * sg;
            float dd = drow[j];
            float Dre = dd * cosang;
            float Dim = -dd * sinang;
            const float* sp2 = spectrum + (l * l + j) * 2 * NREP + 2 * rbase;
#pragma unroll
            for (int r = 0; r < 5; r++) {
                float sre = sp2[2 * r];
                float sim = sp2[2 * r + 1];
                are[r] += Dre * sre - Dim * sim;
                aim[r] += Dre * sim + Dim * sre;
            }
        }
#pragma unroll
        for (int r = 0; r < 5; r++)
            Srot[row * NREP + rbase + r] = make_float2(are[r], aim[r]);
    }
    __syncthreads();

    // --- Phase B: S2 inverse transform -> fp16 quad copies ---
    // 196 threads: each handles grid points (jk0, jk0+98) x 5 reps; one
    // packed LDG.128 per m serves both points.
    if (tid < 196) {
        int jk0 = tid >> 1;
        int rbase = (tid & 1) * 5;
        float acc0[5], acc1[5];
#pragma unroll
        for (int r = 0; r < 5; r++) { acc0[r] = 0.0f; acc1[r] = 0.0f; }
        for (int m = 0; m < MTOT; m++) {
            float4 y = g_Yc4[m * 98 + jk0];
            const float2* s = Srot + m * NREP + rbase;
#pragma unroll
            for (int r = 0; r < 5; r++) {
                float2 sv = s[r];
                acc0[r] += sv.x * y.x - sv.y * y.y;
                acc1[r] += sv.x * y.z - sv.y * y.w;
            }
        }
#pragma unroll
        for (int half = 0; half < 2; half++) {
            int jk = half ? (jk0 + 98) : jk0;
            int j = jk / 14, k = jk % 14;
            int kh = k >> 1;
#pragma unroll
            for (int r = 0; r < 5; r++) {
                int rr = rbase + r;
                __half hv = __float2half(half ? acc1[r] : acc0[r]);
                int rq = rr * SIGQ_R_Q;
                // xp0 copy: quad halves [4q..4q+4) = {top0,top1,bot0,bot1}
                sigH[4 * (rq + (j + 1) * 8 + kh) + (k & 1)] = hv;      // as top
                sigH[4 * (rq + j * 8 + kh) + 2 + (k & 1)] = hv;        // as bottom
                // xp1 copy
                int b = SIGQ_XP_Q + rq;
                if (k & 1) {
                    sigH[4 * (b + (j + 1) * 8 + kh) + 0] = hv;
                    sigH[4 * (b + j * 8 + kh) + 2] = hv;
                } else if (k >= 2) {
                    int hh = kh - 1;
                    sigH[4 * (b + (j + 1) * 8 + hh) + 1] = hv;
                    sigH[4 * (b + j * 8 + hh) + 3] = hv;
                }
            }
        }
    }
    __syncthreads();

    // --- Phases C+D: two row-group passes (out rows 64g..64g+64) ---
    float* outn = out + (size_t)n * 16384;
    const float bias = c_bt[0];
#pragma unroll
    for (int g = 0; g < 2; g++) {
        // Phase C: proj rows [32g-1, 32g+33) -> fp16 proj buffer (10 ch)
        for (int task = tid; task < 34 * PROJ_ROW_W; task += BLOCK) {
            int srow = task / PROJ_ROW_W;
            int w = task - srow * PROJ_ROW_W;
            int grow = 32 * g - 1 + srow;
            unsigned int pofs = (unsigned int)(srow * PROJ_ROW_W + w);
            if ((unsigned)grow >= 64u) {
#pragma unroll
                for (int c = 0; c < NREP; c++) projW[c * PROJ_C_W + pofs] = 0u;
                continue;
            }
            int e = grow * 66 + 2 * w;
            float4 wA = g_tqw[e];
            float4 wB = g_tqw[e + 1];
            int oA = g_tqo[e];
            int oB = g_tqo[e + 1];
#pragma unroll
            for (int c = 0; c < NREP; c++) {
                int rq = c * SIGQ_R_Q;
                uint2 ra = sigQ2[oA + rq];
                uint2 rb = sigQ2[oB + rq];
                float2 at = __half22float2(*(__half2*)&ra.x);
                float2 ab = __half22float2(*(__half2*)&ra.y);
                float2 bt2 = __half22float2(*(__half2*)&rb.x);
                float2 bb = __half22float2(*(__half2*)&rb.y);
                float v0 = wA.x * at.x + wA.y * at.y + wA.z * ab.x + wA.w * ab.y;
                float v1 = wB.x * bt2.x + wB.y * bt2.y + wB.z * bb.x + wB.w * bb.y;
                __half2 pv = __floats2half2_rn(v0, v1);
                projW[c * PROJ_C_W + pofs] = *(unsigned int*)&pv;
            }
        }
        __syncthreads();

        // Phase D: 512 tiles of 4x4 outputs (2 per thread)
#pragma unroll
        for (int t4 = 0; t4 < 2; t4++) {
            int t = tid + t4 * BLOCK;
            int tyl = t >> 5;           // 0..15
            int tx = t & 31;
            float acc[4][4];
#pragma unroll
            for (int dy = 0; dy < 4; dy++)
#pragma unroll
                for (int dx = 0; dx < 4; dx++) acc[dy][dx] = bias;

#pragma unroll
            for (int c = 0; c < NREP; c++) {
                float P[4][4];
#pragma unroll
                for (int yy = 0; yy < 4; yy++) {
                    unsigned int base = (unsigned int)(c * PROJ_C_W + (2 * tyl + yy) * PROJ_ROW_W + tx);
                    float2 ab = __half22float2(*(__half2*)&projW[base]);
                    float2 cd = __half22float2(*(__half2*)&projW[base + 1]);
                    P[yy][0] = ab.x; P[yy][1] = ab.y;
                    P[yy][2] = cd.x; P[yy][3] = cd.y;
                }
#pragma unroll
                for (int dy = 0; dy < 4; dy++) {
                    int pl = dy >> 1;
                    int py = dy & 1;
                    int ry0 = py ? pl + 2 : pl + 1;
                    int ry1 = py ? pl + 1 : pl;
                    int kya = py ? 0 : 1;
                    int kyb = py ? 2 : 3;
#pragma unroll
                    for (int dx = 0; dx < 4; dx++) {
                        int ql = dx >> 1;
                        int px = dx & 1;
                        int rx0 = px ? ql + 2 : ql + 1;
                        int rx1 = px ? ql + 1 : ql;
                        int kxa = px ? 0 : 1;
                        int kxb = px ? 2 : 3;
                        acc[dy][dx] += P[ry0][rx0] * c_wt[c * 16 + kya * 4 + kxa]
                                     + P[ry0][rx1] * c_wt[c * 16 + kya * 4 + kxb]
                                     + P[ry1][rx0] * c_wt[c * 16 + kyb * 4 + kxa]
                                     + P[ry1][rx1] * c_wt[c * 16 + kyb * 4 + kxb];
                    }
                }
            }
            int orow0 = 64 * g + 4 * tyl;
#pragma unroll
            for (int dy = 0; dy < 4; dy++) {
                float4 v = make_float4(acc[dy][0], acc[dy][1], acc[dy][2], acc[dy][3]);
                *reinterpret_cast<float4*>(outn + (size_t)(orow0 + dy) * 128 + 4 * tx) = v;
            }
        }
        if (g == 0) __syncthreads();   // protect proj before pass-1's C
    }
}

// ---------------------------------------------------------------------------
extern "C" void kernel_launch(void* const* d_in, const int* in_sizes, int n_in,
                              void* d_out, int out_size) {
    const float* angles   = (const float*)d_in[0];
    const float* spectrum = (const float*)d_in[1];
    const float* wt       = (const float*)d_in[2];
    const float* bt       = (const float*)d_in[3];
    float* out = (float*)d_out;

    cudaFuncSetAttribute(decoder_kernel,
                         cudaFuncAttributeMaxDynamicSharedMemorySize, SMEM_BYTES);

    cudaMemcpyToSymbolAsync(c_wt, wt, 160 * sizeof(float), 0,
                            cudaMemcpyDeviceToDevice);
    cudaMemcpyToSymbolAsync(c_bt, bt, sizeof(float), 0,
                            cudaMemcpyDeviceToDevice);

    // 64 blocks x 256 = 16384 threads: covers taps up to 8192+4224=12416.
    setup_kernel<<<64, 256>>>();
    decoder_kernel<<<NPOSE, BLOCK, SMEM_BYTES>>>(angles, spectrum, out);
}

// round 12
// speedup vs baseline: 2.2241x; 1.0536x over previous
#include <cuda_runtime.h>
#include <cuda_fp16.h>
#include <math.h>

// ---------------------------------------------------------------------------
// ProjectionDecoder: Wigner rotate -> S2 ifft -> grid_sample -> convtranspose
// angles (2048,3) f32; spectrum (49,10,2) f32; wt (10,1,4,4) f32; bt (1) f32
// out (2048,1,128,128) f32
//
// R12: LSU-instruction diet. proj transposed [c][word][srow] so phase D uses
// LDS.128+LDS.64 per (channel,word) on 8x4-output tall tiles; phase B reads
// Srot rows as 5 LDS.128 (1 jk x 10 reps per thread); Wigner term table and
// tap tables packed/transposed for 1-instr coalesced loads.
// ---------------------------------------------------------------------------

#define NPOSE 2048
#define MTOT  49
#define NREP  10
#define NJK   196     // 14*14
#define NSLOT 4753    // sum (2l+1)^3, l=0..6
#define BLOCK 256

// sigQ (fp16): [xp(2)][r(10)][yq(15)][hh(8)] quads; each quad = 2 words
#define SIGQ_XP_Q   1200
#define SIGQ_R_Q    120
#define SIGQ_TOT_Q  2400
#define SIGQ_TOT_W  4800

// proj (per pass): [c(10)][word(33)][srow(36 padded, 34 used)] half2 words
#define PROJ_SROW   36
#define PROJ_W_CNT  33
#define PROJ_C_W    (PROJ_W_CNT * PROJ_SROW)   // 1188
#define PROJ_TOT_W  (NREP * PROJ_C_W)          // 11880

__device__ float2      g_tterm[NSLOT];     // {coef, bits(pc<<8|ps)}
__device__ float2      g_Yc[MTOT * NJK];   // {Yre, Yim}
__device__ float4      g_tqwT[66 * 64];    // quad weights, [h][row]
__device__ int2        g_tqoT[33 * 64];    // quad offsets {oA,oB}, [w][row]

__constant__ float  c_wt[160];   // deconv weights (10 x 16)
__constant__ float  c_bt[1];     // bias
__constant__ double c_fact[13] = {
    1.0, 1.0, 2.0, 6.0, 24.0, 120.0, 720.0, 5040.0,
    40320.0, 362880.0, 3628800.0, 39916800.0, 479001600.0 };

__device__ __forceinline__ int slotbase(int l) { return l * l * (2 * l * l - 1); }
__device__ __forceinline__ int dloff(int l) { return l * (4 * l * l - 1) / 3; }

#define PI_F 3.14159265358979323846f

// ---------------------------------------------------------------------------
// Setup kernel: input-independent tables.
// ---------------------------------------------------------------------------
__global__ void setup_kernel() {
    int g = blockIdx.x * blockDim.x + threadIdx.x;

    if (g < NSLOT) {
        int l = (g >= 1) + (g >= 28) + (g >= 153) + (g >= 496) + (g >= 1225) + (g >= 2556);
        int n1 = 2 * l + 1;
        int rem = g - slotbase(l);
        int i = rem / (n1 * n1);
        int j = (rem / n1) % n1;
        int k = rem % n1;
        int mp = i - l, m = j - l;
        int kmin = max(0, m - mp);
        int kmax = min(l + m, l - mp);
        float coef = 0.0f;
        int pc = 0, ps = 0;
        if (k >= kmin && k <= kmax) {
            double pref = sqrt(c_fact[l + mp] * c_fact[l - mp] * c_fact[l + m] * c_fact[l - m]);
            double c = pref / (c_fact[l + m - k] * c_fact[k] * c_fact[l - mp - k] * c_fact[mp - m + k]);
            if ((mp - m + k) & 1) c = -c;
            coef = (float)c;
            pc = 2 * l + m - mp - 2 * k;
            ps = mp - m + 2 * k;
        }
        g_tterm[g] = make_float2(coef, __int_as_float((pc << 8) | ps));
    } else if (g >= 5120 && g < 5120 + NJK) {
        // Spherical harmonic table Y (49, 14, 14)
        int jk = g - 5120;
        int j = jk / 14, k = jk % 14;
        float beta = PI_F * (2.0f * j + 1.0f) / 28.0f;
        float x, sx;
        sincosf(beta, &sx, &x);
        float P[7][7];
#pragma unroll
        for (int a = 0; a < 7; a++)
#pragma unroll
            for (int b = 0; b < 7; b++) P[a][b] = 0.0f;
        P[0][0] = 1.0f;
        for (int m = 1; m <= 6; m++) P[m][m] = -(2.0f * m - 1.0f) * sx * P[m - 1][m - 1];
        for (int m = 0; m <= 6; m++) {
            if (m + 1 <= 6) P[m + 1][m] = (2.0f * m + 1.0f) * x * P[m][m];
            for (int l = m + 2; l <= 6; l++)
                P[l][m] = ((2.0f * l - 1.0f) * x * P[l - 1][m] - (l + m - 1.0f) * P[l - 2][m]) / (float)(l - m);
        }
        float alk = 2.0f * PI_F * (float)k / 14.0f;
        for (int l = 0; l <= 6; l++) {
            for (int m = 0; m <= l; m++) {
                float Nn = sqrtf((2.0f * l + 1.0f) / (4.0f * PI_F)
                                 * (float)(c_fact[l - m] / c_fact[l + m]));
                float pr = Nn * P[l][m];
                float sm_, cm_;
                sincosf((float)m * alk, &sm_, &cm_);
                float yre = pr * cm_;
                float yim = pr * sm_;
                g_Yc[(l * l + l + m) * NJK + jk] = make_float2(yre, yim);
                if (m > 0) {
                    float sgn = (m & 1) ? -1.0f : 1.0f;
                    g_Yc[(l * l + l - m) * NJK + jk] = make_float2(sgn * yre, -sgn * yim);
                }
            }
        }
    } else if (g >= 8192 && g < 8192 + 64 * 66) {
        // Quad tap entry for (proj row, stored h), TRANSPOSED tables.
        int idx = g - 8192;
        int row = idx / 66;
        int h = idx % 66;
        int col = h - 1;
        float4 w4 = make_float4(0.f, 0.f, 0.f, 0.f);
        int off = 0;
        if (col >= 0 && col < 64) {
            float step = 1.6f / 63.0f;
            float yv = -0.8f + row * step;
            float xv = -0.8f + col * step;
            float rho = sqrtf(xv * xv + yv * yv);
            float th = asinf(fminf(rho, 1.0f));
            float ph = atan2f(yv, xv);
            float gx = ph / PI_F;
            float gy = 2.0f * th / PI_F - 1.0f;
            float gpx = (gx + 1.0f) * 7.0f - 0.5f;
            float gpy = (gy + 1.0f) * 7.0f - 0.5f;
            float x0f = floorf(gpx), y0f = floorf(gpy);
            int x0 = (int)x0f, y0 = (int)y0f;   // in [-1,13]
            float fx = gpx - x0f, fy = gpy - y0f;
            float wx0 = 1.0f - fx, wx1 = fx;
            float wy0 = 1.0f - fy, wy1 = fy;
            float vy0 = (y0 >= 0) ? 1.0f : 0.0f;
            float vy1 = (y0 + 1 <= 13) ? 1.0f : 0.0f;
            int xp, hh;
            if (x0 >= 0) {
                float vx1 = (x0 + 1 <= 13) ? 1.0f : 0.0f;
                xp = x0 & 1;
                hh = x0 >> 1;
                w4 = make_float4(wx0 * wy0 * vy0, wx1 * wy0 * vx1 * vy0,
                                 wx0 * wy1 * vy1, wx1 * wy1 * vx1 * vy1);
            } else {  // x0 == -1
                xp = 0; hh = 0;
                w4 = make_float4(wx1 * wy0 * vy0, 0.0f,
                                 wx1 * wy1 * vy1, 0.0f);
            }
            off = xp * SIGQ_XP_Q + (y0 + 1) * 8 + hh;
        }
        g_tqwT[h * 64 + row] = w4;
        ((int*)g_tqoT)[((h >> 1) * 64 + row) * 2 + (h & 1)] = off;
    }
}

// ---------------------------------------------------------------------------
// Main fused kernel: one block (256 threads) per pose n, 3 blocks/SM.
// smem word layout (4B words):
//   dS [0,455)  cpow [455,468)  spow [468,481)
//   cA [481,488) sA [488,495) cG [495,502) sG [502,509)
//   Srot  [512,1492)    rotated spectrum float2 (49 x 10), float4-readable
//   sigQ  [1492,6292)   fp16 quads, uint2 each
//   proj  [6292,18172)  fp16 projection [c][word][srow36]
#define SIGQ_OFF  1492
#define PROJ_OFF  6292
#define SMEM_WORDS 18172
#define SMEM_BYTES (SMEM_WORDS * 4)

__global__ void __launch_bounds__(BLOCK, 3)
decoder_kernel(const float* __restrict__ angles,
               const float* __restrict__ spectrum,
               float* __restrict__ out) {
    extern __shared__ float sm[];
    float*  dS   = sm;
    float*  cpow = sm + 455;
    float*  spow = sm + 468;
    float*  cA   = sm + 481;
    float*  sA   = sm + 488;
    float*  cG   = sm + 495;
    float*  sG   = sm + 502;
    float2* Srot = (float2*)(sm + 512);
    const float4* Srot4 = (const float4*)(sm + 512);
    unsigned int* sigQW = (unsigned int*)(sm + SIGQ_OFF);
    __half* sigH = (__half*)(sm + SIGQ_OFF);
    const uint2* sigQ2 = (const uint2*)(sm + SIGQ_OFF);
    unsigned int* projW = (unsigned int*)(sm + PROJ_OFF);

    const int n = blockIdx.x;
    const int tid = threadIdx.x;

    const float alpha = angles[3 * n + 0];
    const float beta  = angles[3 * n + 1];
    const float gamma = angles[3 * n + 2];

    // --- Phase A0: trig tables, zero sig quads ---
    if (tid < 7) {
        float s, c;
        sincosf((float)tid * alpha, &s, &c);
        cA[tid] = c; sA[tid] = s;
    } else if (tid < 14) {
        int m = tid - 7;
        float s, c;
        sincosf((float)m * gamma, &s, &c);
        cG[m] = c; sG[m] = s;
    } else if (tid == 14) {
        float sb, cb;
        sincosf(0.5f * beta, &sb, &cb);
        float cp = 1.0f, spw = 1.0f;
#pragma unroll
        for (int e = 0; e < 13; e++) {
            cpow[e] = cp; spow[e] = spw;
            cp *= cb; spw *= sb;
        }
    }
    for (int i = tid; i < SIGQ_TOT_W; i += BLOCK) sigQW[i] = 0u;
    __syncthreads();

    // --- Phase A1: Wigner small-d matrices (packed term table) ---
    for (int t = tid; t < 455; t += BLOCK) {
        int l = (t >= 1) + (t >= 10) + (t >= 35) + (t >= 84) + (t >= 165) + (t >= 286);
        int n1 = 2 * l + 1;
        int loc = t - dloff(l);
        int base = slotbase(l) + loc * n1;
        float sum = 0.0f;
        for (int k = 0; k < n1; k++) {
            float2 tm = g_tterm[base + k];
            int bits = __float_as_int(tm.y);
            sum += tm.x * cpow[bits >> 8] * spow[bits & 255];
        }
        dS[t] = sum;
    }
    __syncthreads();

    // --- Phase A2: complex Wigner-D rotate ---
    if (tid < 2 * MTOT) {
        int row = tid >> 1;
        int rbase = (tid & 1) * 5;
        int l = (row >= 1) + (row >= 4) + (row >= 9) + (row >= 16) + (row >= 25) + (row >= 36);
        int i = row - l * l;
        int mp = i - l;
        int n1 = 2 * l + 1;
        float camp = cA[mp < 0 ? -mp : mp];
        float samp = mp < 0 ? -sA[-mp] : sA[mp];
        float are[5], aim[5];
#pragma unroll
        for (int r = 0; r < 5; r++) { are[r] = 0.0f; aim[r] = 0.0f; }
        const float* drow = dS + dloff(l) + i * n1;
        for (int j = 0; j < n1; j++) {
            int m = j - l;
            float cg = cG[m < 0 ? -m : m];
            float sg = m < 0 ? -sG[-m] : sG[m];
            float cosang = camp * cg - samp * sg;
            float sinang = samp * cg + camp * sg;
            float dd = drow[j];
            float Dre = dd * cosang;
            float Dim = -dd * sinang;
            const float* sp2 = spectrum + (l * l + j) * 2 * NREP + 2 * rbase;
#pragma unroll
            for (int r = 0; r < 5; r++) {
                float sre = sp2[2 * r];
                float sim = sp2[2 * r + 1];
                are[r] += Dre * sre - Dim * sim;
                aim[r] += Dre * sim + Dim * sre;
            }
        }
#pragma unroll
        for (int r = 0; r < 5; r++)
            Srot[row * NREP + rbase + r] = make_float2(are[r], aim[r]);
    }
    __syncthreads();

    // --- Phase B: S2 inverse transform -> fp16 quad copies ---
    // 196 threads: 1 jk x 10 reps each; Srot row = 5 LDS.128.
    if (tid < NJK) {
        int jk = tid;
        float acc[NREP];
#pragma unroll
        for (int r = 0; r < NREP; r++) acc[r] = 0.0f;
        for (int m = 0; m < MTOT; m++) {
            float2 y = g_Yc[m * NJK + jk];
            float4 s01 = Srot4[m * 5 + 0];
            float4 s23 = Srot4[m * 5 + 1];
            float4 s45 = Srot4[m * 5 + 2];
            float4 s67 = Srot4[m * 5 + 3];
            float4 s89 = Srot4[m * 5 + 4];
            acc[0] += s01.x * y.x - s01.y * y.y;
            acc[1] += s01.z * y.x - s01.w * y.y;
            acc[2] += s23.x * y.x - s23.y * y.y;
            acc[3] += s23.z * y.x - s23.w * y.y;
            acc[4] += s45.x * y.x - s45.y * y.y;
            acc[5] += s45.z * y.x - s45.w * y.y;
            acc[6] += s67.x * y.x - s67.y * y.y;
            acc[7] += s67.z * y.x - s67.w * y.y;
            acc[8] += s89.x * y.x - s89.y * y.y;
            acc[9] += s89.z * y.x - s89.w * y.y;
        }
        int j = jk / 14, k = jk % 14;
        int kh = k >> 1;
#pragma unroll
        for (int r = 0; r < NREP; r++) {
            __half hv = __float2half(acc[r]);
            int rq = r * SIGQ_R_Q;
            sigH[4 * (rq + (j + 1) * 8 + kh) + (k & 1)] = hv;      // as top
            sigH[4 * (rq + j * 8 + kh) + 2 + (k & 1)] = hv;        // as bottom
            int b = SIGQ_XP_Q + rq;
            if (k & 1) {
                sigH[4 * (b + (j + 1) * 8 + kh) + 0] = hv;
                sigH[4 * (b + j * 8 + kh) + 2] = hv;
            } else if (k >= 2) {
                int hh = kh - 1;
                sigH[4 * (b + (j + 1) * 8 + hh) + 1] = hv;
                sigH[4 * (b + j * 8 + hh) + 3] = hv;
            }
        }
    }
    __syncthreads();

    // --- Phases C+D: two row-group passes (out rows 64g..64g+64) ---
    float* outn = out + (size_t)n * 16384;
    const float bias = c_bt[0];
#pragma unroll 1
    for (int g = 0; g < 2; g++) {
        // Phase C: proj rows [32g-1, 32g+33) -> transposed fp16 proj
        // task: srow fastest (lanes share word w -> stride-1 STS)
        for (int task = tid; task < 33 * 34; task += BLOCK) {
            int w = task / 34;
            int srow = task - w * 34;
            int grow = 32 * g - 1 + srow;
            if ((unsigned)grow >= 64u) {
#pragma unroll
                for (int c = 0; c < NREP; c++)
                    projW[(c * 33 + w) * PROJ_SROW + srow] = 0u;
                continue;
            }
            int2 o2 = g_tqoT[w * 64 + grow];
            float4 wA = g_tqwT[(2 * w) * 64 + grow];
            float4 wB = g_tqwT[(2 * w + 1) * 64 + grow];
#pragma unroll
            for (int c = 0; c < NREP; c++) {
                int rq = c * SIGQ_R_Q;
                uint2 ra = sigQ2[o2.x + rq];
                uint2 rb = sigQ2[o2.y + rq];
                float2 at = __half22float2(*(__half2*)&ra.x);
                float2 ab = __half22float2(*(__half2*)&ra.y);
                float2 bt2 = __half22float2(*(__half2*)&rb.x);
                float2 bb = __half22float2(*(__half2*)&rb.y);
                float v0 = wA.x * at.x + wA.y * at.y + wA.z * ab.x + wA.w * ab.y;
                float v1 = wB.x * bt2.x + wB.y * bt2.y + wB.z * bb.x + wB.w * bb.y;
                __half2 pv = __floats2half2_rn(v0, v1);
                projW[(c * 33 + w) * PROJ_SROW + srow] = *(unsigned int*)&pv;
            }
        }
        __syncthreads();

        // Phase D: one 8x4 output tile per thread
        {
            int b = tid >> 5;           // 0..7
            int tx = tid & 31;
            float acc[8][4];
#pragma unroll
            for (int dy = 0; dy < 8; dy++)
#pragma unroll
                for (int dx = 0; dx < 4; dx++) acc[dy][dx] = bias;

#pragma unroll
            for (int c = 0; c < NREP; c++) {
                float P[6][4];
#pragma unroll
                for (int wi = 0; wi < 2; wi++) {
                    int base = (c * 33 + tx + wi) * PROJ_SROW + 4 * b;
                    uint4 q  = *(const uint4*)&projW[base];
                    uint2 q2 = *(const uint2*)&projW[base + 4];
                    float2 f0 = __half22float2(*(__half2*)&q.x);
                    float2 f1 = __half22float2(*(__half2*)&q.y);
                    float2 f2 = __half22float2(*(__half2*)&q.z);
                    float2 f3 = __half22float2(*(__half2*)&q.w);
                    float2 f4 = __half22float2(*(__half2*)&q2.x);
                    float2 f5 = __half22float2(*(__half2*)&q2.y);
                    P[0][2 * wi] = f0.x; P[0][2 * wi + 1] = f0.y;
                    P[1][2 * wi] = f1.x; P[1][2 * wi + 1] = f1.y;
                    P[2][2 * wi] = f2.x; P[2][2 * wi + 1] = f2.y;
                    P[3][2 * wi] = f3.x; P[3][2 * wi + 1] = f3.y;
                    P[4][2 * wi] = f4.x; P[4][2 * wi + 1] = f4.y;
                    P[5][2 * wi] = f5.x; P[5][2 * wi + 1] = f5.y;
                }
#pragma unroll
                for (int dy = 0; dy < 8; dy++) {
                    int pl = dy >> 1;
                    int py = dy & 1;
                    int ry0 = py ? pl + 2 : pl + 1;
                    int ry1 = py ? pl + 1 : pl;
                    int kya = py ? 0 : 1;
                    int kyb = py ? 2 : 3;
#pragma unroll
                    for (int dx = 0; dx < 4; dx++) {
                        int ql = dx >> 1;
                        int px = dx & 1;
                        int rx0 = px ? ql + 2 : ql + 1;
                        int rx1 = px ? ql + 1 : ql;
                        int kxa = px ? 0 : 1;
                        int kxb = px ? 2 : 3;
                        acc[dy][dx] += P[ry0][rx0] * c_wt[c * 16 + kya * 4 + kxa]
                                     + P[ry0][rx1] * c_wt[c * 16 + kya * 4 + kxb]
                                     + P[ry1][rx0] * c_wt[c * 16 + kyb * 4 + kxa]
                                     + P[ry1][rx1] * c_wt[c * 16 + kyb * 4 + kxb];
                    }
                }
            }
            int orow0 = 64 * g + 8 * b;
#pragma unroll
            for (int dy = 0; dy < 8; dy++) {
                float4 v = make_float4(acc[dy][0], acc[dy][1], acc[dy][2], acc[dy][3]);
                *reinterpret_cast<float4*>(outn + (size_t)(orow0 + dy) * 128 + 4 * tx) = v;
            }
        }
        if (g == 0) __syncthreads();   // protect proj before pass-1's C
    }
}

// ---------------------------------------------------------------------------
extern "C" void kernel_launch(void* const* d_in, const int* in_sizes, int n_in,
                              void* d_out, int out_size) {
    const float* angles   = (const float*)d_in[0];
    const float* spectrum = (const float*)d_in[1];
    const float* wt       = (const float*)d_in[2];
    const float* bt       = (const float*)d_in[3];
    float* out = (float*)d_out;

    cudaFuncSetAttribute(decoder_kernel,
                         cudaFuncAttributeMaxDynamicSharedMemorySize, SMEM_BYTES);

    cudaMemcpyToSymbolAsync(c_wt, wt, 160 * sizeof(float), 0,
                            cudaMemcpyDeviceToDevice);
    cudaMemcpyToSymbolAsync(c_bt, bt, sizeof(float), 0,
                            cudaMemcpyDeviceToDevice);

    // 64 blocks x 256 = 16384 threads: covers taps up to 8192+4224=12416.
    setup_kernel<<<64, 256>>>();
    decoder_kernel<<<NPOSE, BLOCK, SMEM_BYTES>>>(angles, spectrum, out);
}

// round 13
// speedup vs baseline: 2.4281x; 1.0917x over previous
#include <cuda_runtime.h>
#include <cuda_fp16.h>
#include <math.h>

// ---------------------------------------------------------------------------
// ProjectionDecoder: Wigner rotate -> S2 ifft -> grid_sample -> convtranspose
// angles (2048,3) f32; spectrum (49,10,2) f32; wt (10,1,4,4) f32; bt (1) f32
// out (2048,1,128,128) f32
//
// R13: packed fp32x2 math (fma.rn.f32x2 / FFMA2) in phases B and D halves
// FMA-pipe instruction count at full fp32 precision. Srot split into re/im
// planes (padded rows) so phase-B packed operands load directly as
// ulonglong2; phase-D accumulators packed along dy-pairs.
// ---------------------------------------------------------------------------

#define NPOSE 2048
#define MTOT  49
#define NREP  10
#define NJK   196     // 14*14
#define NSLOT 4753    // sum (2l+1)^3, l=0..6
#define BLOCK 256

// sigQ (fp16): [xp(2)][r(10)][yq(15)][hh(8)] quads; each quad = 2 words
#define SIGQ_XP_Q   1200
#define SIGQ_R_Q    120
#define SIGQ_TOT_Q  2400
#define SIGQ_TOT_W  4800

// proj (per pass): [c(10)][word(33)][srow(36 padded, 34 used)] half2 words
#define PROJ_SROW   36
#define PROJ_W_CNT  33
#define PROJ_C_W    (PROJ_W_CNT * PROJ_SROW)   // 1188
#define PROJ_TOT_W  (NREP * PROJ_C_W)          // 11880

__device__ float2      g_tterm[NSLOT];     // {coef, bits(pc<<8|ps)}
__device__ float2      g_Yc[MTOT * NJK];   // {Yre, Yim}
__device__ float4      g_tqwT[66 * 64];    // quad weights, [h][row]
__device__ int2        g_tqoT[33 * 64];    // quad offsets {oA,oB}, [w][row]

__constant__ float  c_wt[160];   // deconv weights (10 x 16)
__constant__ float  c_bt[1];     // bias
__constant__ double c_fact[13] = {
    1.0, 1.0, 2.0, 6.0, 24.0, 120.0, 720.0, 5040.0,
    40320.0, 362880.0, 3628800.0, 39916800.0, 479001600.0 };

__device__ __forceinline__ int slotbase(int l) { return l * l * (2 * l * l - 1); }
__device__ __forceinline__ int dloff(int l) { return l * (4 * l * l - 1) / 3; }

// --- packed fp32x2 helpers (FFMA2 path; ptxas never emits from C++) ---
__device__ __forceinline__ unsigned long long pk2(float lo, float hi) {
    unsigned long long r;
    asm("mov.b64 %0, {%1, %2};" : "=l"(r) : "f"(lo), "f"(hi));
    return r;
}
__device__ __forceinline__ void fma2(unsigned long long& d,
                                     unsigned long long a,
                                     unsigned long long b) {
    asm("fma.rn.f32x2 %0, %1, %2, %0;" : "+l"(d) : "l"(a), "l"(b));
}
__device__ __forceinline__ float2 upk2(unsigned long long v) {
    float lo, hi;
    asm("mov.b64 {%0, %1}, %2;" : "=f"(lo), "=f"(hi) : "l"(v));
    return make_float2(lo, hi);
}

#define PI_F 3.14159265358979323846f

// ---------------------------------------------------------------------------
// Setup kernel: input-independent tables.
// ---------------------------------------------------------------------------
__global__ void setup_kernel() {
    int g = blockIdx.x * blockDim.x + threadIdx.x;

    if (g < NSLOT) {
        int l = (g >= 1) + (g >= 28) + (g >= 153) + (g >= 496) + (g >= 1225) + (g >= 2556);
        int n1 = 2 * l + 1;
        int rem = g - slotbase(l);
        int i = rem / (n1 * n1);
        int j = (rem / n1) % n1;
        int k = rem % n1;
        int mp = i - l, m = j - l;
        int kmin = max(0, m - mp);
        int kmax = min(l + m, l - mp);
        float coef = 0.0f;
        int pc = 0, ps = 0;
        if (k >= kmin && k <= kmax) {
            double pref = sqrt(c_fact[l + mp] * c_fact[l - mp] * c_fact[l + m] * c_fact[l - m]);
            double c = pref / (c_fact[l + m - k] * c_fact[k] * c_fact[l - mp - k] * c_fact[mp - m + k]);
            if ((mp - m + k) & 1) c = -c;
            coef = (float)c;
            pc = 2 * l + m - mp - 2 * k;
            ps = mp - m + 2 * k;
        }
        g_tterm[g] = make_float2(coef, __int_as_float((pc << 8) | ps));
    } else if (g >= 5120 && g < 5120 + NJK) {
        // Spherical harmonic table Y (49, 14, 14)
        int jk = g - 5120;
        int j = jk / 14, k = jk % 14;
        float beta = PI_F * (2.0f * j + 1.0f) / 28.0f;
        float x, sx;
        sincosf(beta, &sx, &x);
        float P[7][7];
#pragma unroll
        for (int a = 0; a < 7; a++)
#pragma unroll
            for (int b = 0; b < 7; b++) P[a][b] = 0.0f;
        P[0][0] = 1.0f;
        for (int m = 1; m <= 6; m++) P[m][m] = -(2.0f * m - 1.0f) * sx * P[m - 1][m - 1];
        for (int m = 0; m <= 6; m++) {
            if (m + 1 <= 6) P[m + 1][m] = (2.0f * m + 1.0f) * x * P[m][m];
            for (int l = m + 2; l <= 6; l++)
                P[l][m] = ((2.0f * l - 1.0f) * x * P[l - 1][m] - (l + m - 1.0f) * P[l - 2][m]) / (float)(l - m);
        }
        float alk = 2.0f * PI_F * (float)k / 14.0f;
        for (int l = 0; l <= 6; l++) {
            for (int m = 0; m <= l; m++) {
                float Nn = sqrtf((2.0f * l + 1.0f) / (4.0f * PI_F)
                                 * (float)(c_fact[l - m] / c_fact[l + m]));
                float pr = Nn * P[l][m];
                float sm_, cm_;
                sincosf((float)m * alk, &sm_, &cm_);
                float yre = pr * cm_;
                float yim = pr * sm_;
                g_Yc[(l * l + l + m) * NJK + jk] = make_float2(yre, yim);
                if (m > 0) {
                    float sgn = (m & 1) ? -1.0f : 1.0f;
                    g_Yc[(l * l + l - m) * NJK + jk] = make_float2(sgn * yre, -sgn * yim);
                }
            }
        }
    } else if (g >= 8192 && g < 8192 + 64 * 66) {
        // Quad tap entry for (proj row, stored h), TRANSPOSED tables.
        int idx = g - 8192;
        int row = idx / 66;
        int h = idx % 66;
        int col = h - 1;
        float4 w4 = make_float4(0.f, 0.f, 0.f, 0.f);
        int off = 0;
        if (col >= 0 && col < 64) {
            float step = 1.6f / 63.0f;
            float yv = -0.8f + row * step;
            float xv = -0.8f + col * step;
            float rho = sqrtf(xv * xv + yv * yv);
            float th = asinf(fminf(rho, 1.0f));
            float ph = atan2f(yv, xv);
            float gx = ph / PI_F;
            float gy = 2.0f * th / PI_F - 1.0f;
            float gpx = (gx + 1.0f) * 7.0f - 0.5f;
            float gpy = (gy + 1.0f) * 7.0f - 0.5f;
            float x0f = floorf(gpx), y0f = floorf(gpy);
            int x0 = (int)x0f, y0 = (int)y0f;   // in [-1,13]
            float fx = gpx - x0f, fy = gpy - y0f;
            float wx0 = 1.0f - fx, wx1 = fx;
            float wy0 = 1.0f - fy, wy1 = fy;
            float vy0 = (y0 >= 0) ? 1.0f : 0.0f;
            float vy1 = (y0 + 1 <= 13) ? 1.0f : 0.0f;
            int xp, hh;
            if (x0 >= 0) {
                float vx1 = (x0 + 1 <= 13) ? 1.0f : 0.0f;
                xp = x0 & 1;
                hh = x0 >> 1;
                w4 = make_float4(wx0 * wy0 * vy0, wx1 * wy0 * vx1 * vy0,
                                 wx0 * wy1 * vy1, wx1 * wy1 * vx1 * vy1);
            } else {  // x0 == -1
                xp = 0; hh = 0;
                w4 = make_float4(wx1 * wy0 * vy0, 0.0f,
                                 wx1 * wy1 * vy1, 0.0f);
            }
            off = xp * SIGQ_XP_Q + (y0 + 1) * 8 + hh;
        }
        g_tqwT[h * 64 + row] = w4;
        ((int*)g_tqoT)[((h >> 1) * 64 + row) * 2 + (h & 1)] = off;
    }
}

// ---------------------------------------------------------------------------
// Main fused kernel: one block (256 threads) per pose n, 3 blocks/SM.
// smem word layout (4B words):
//   dS [0,455)  cpow [455,468)  spow [468,481)
//   cA [481,488) sA [488,495) cG [495,502) sG [502,509)
//   SrotRe [512,1100)   re plane, 49 rows x 12 (10 used), 16B-aligned rows
//   SrotIm [1100,1688)  im plane, same shape
//   sigQ   [1688,6488)  fp16 quads, uint2 each
//   proj   [6488,18368) fp16 projection [c][word][srow36]
#define SROT_RE   512
#define SROT_IM   1100
#define SIGQ_OFF  1688
#define PROJ_OFF  6488
#define SMEM_WORDS 18368
#define SMEM_BYTES (SMEM_WORDS * 4)

__global__ void __launch_bounds__(BLOCK, 3)
decoder_kernel(const float* __restrict__ angles,
               const float* __restrict__ spectrum,
               float* __restrict__ out) {
    extern __shared__ float sm[];
    float*  dS   = sm;
    float*  cpow = sm + 455;
    float*  spow = sm + 468;
    float*  cA   = sm + 481;
    float*  sA   = sm + 488;
    float*  cG   = sm + 495;
    float*  sG   = sm + 502;
    float*  smre = sm + SROT_RE;
    float*  smim = sm + SROT_IM;
    unsigned int* sigQW = (unsigned int*)(sm + SIGQ_OFF);
    __half* sigH = (__half*)(sm + SIGQ_OFF);
    const uint2* sigQ2 = (const uint2*)(sm + SIGQ_OFF);
    unsigned int* projW = (unsigned int*)(sm + PROJ_OFF);

    const int n = blockIdx.x;
    const int tid = threadIdx.x;

    const float alpha = angles[3 * n + 0];
    const float beta  = angles[3 * n + 1];
    const float gamma = angles[3 * n + 2];

    // --- Phase A0: trig tables, zero sig quads ---
    if (tid < 7) {
        float s, c;
        sincosf((float)tid * alpha, &s, &c);
        cA[tid] = c; sA[tid] = s;
    } else if (tid < 14) {
        int m = tid - 7;
        float s, c;
        sincosf((float)m * gamma, &s, &c);
        cG[m] = c; sG[m] = s;
    } else if (tid == 14) {
        float sb, cb;
        sincosf(0.5f * beta, &sb, &cb);
        float cp = 1.0f, spw = 1.0f;
#pragma unroll
        for (int e = 0; e < 13; e++) {
            cpow[e] = cp; spow[e] = spw;
            cp *= cb; spw *= sb;
        }
    }
    for (int i = tid; i < SIGQ_TOT_W; i += BLOCK) sigQW[i] = 0u;
    __syncthreads();

    // --- Phase A1: Wigner small-d matrices (packed term table) ---
    for (int t = tid; t < 455; t += BLOCK) {
        int l = (t >= 1) + (t >= 10) + (t >= 35) + (t >= 84) + (t >= 165) + (t >= 286);
        int n1 = 2 * l + 1;
        int loc = t - dloff(l);
        int base = slotbase(l) + loc * n1;
        float sum = 0.0f;
        for (int k = 0; k < n1; k++) {
            float2 tm = g_tterm[base + k];
            int bits = __float_as_int(tm.y);
            sum += tm.x * cpow[bits >> 8] * spow[bits & 255];
        }
        dS[t] = sum;
    }
    __syncthreads();

    // --- Phase A2: complex Wigner-D rotate -> re/im planes ---
    if (tid < 2 * MTOT) {
        int row = tid >> 1;
        int rbase = (tid & 1) * 5;
        int l = (row >= 1) + (row >= 4) + (row >= 9) + (row >= 16) + (row >= 25) + (row >= 36);
        int i = row - l * l;
        int mp = i - l;
        int n1 = 2 * l + 1;
        float camp = cA[mp < 0 ? -mp : mp];
        float samp = mp < 0 ? -sA[-mp] : sA[mp];
        float are[5], aim[5];
#pragma unroll
        for (int r = 0; r < 5; r++) { are[r] = 0.0f; aim[r] = 0.0f; }
        const float* drow = dS + dloff(l) + i * n1;
        for (int j = 0; j < n1; j++) {
            int m = j - l;
            float cg = cG[m < 0 ? -m : m];
            float sg = m < 0 ? -sG[-m] : sG[m];
            float cosang = camp * cg - samp * sg;
            float sinang = samp * cg + camp * sg;
            float dd = drow[j];
            float Dre = dd * cosang;
            float Dim = -dd * sinang;
            const float* sp2 = spectrum + (l * l + j) * 2 * NREP + 2 * rbase;
#pragma unroll
            for (int r = 0; r < 5; r++) {
                float sre = sp2[2 * r];
                float sim = sp2[2 * r + 1];
                are[r] += Dre * sre - Dim * sim;
                aim[r] += Dre * sim + Dim * sre;
            }
        }
#pragma unroll
        for (int r = 0; r < 5; r++) {
            smre[row * 12 + rbase + r] = are[r];
            smim[row * 12 + rbase + r] = aim[r];
        }
    }
    __syncthreads();

    // --- Phase B: S2 inverse transform (FFMA2) -> fp16 quad copies ---
    if (tid < NJK) {
        int jk = tid;
        unsigned long long acc2[5];
        unsigned long long z = pk2(0.0f, 0.0f);
#pragma unroll
        for (int p = 0; p < 5; p++) acc2[p] = z;
        const ulonglong2* re2 = (const ulonglong2*)smre;
        const ulonglong2* im2 = (const ulonglong2*)smim;
        const unsigned long long* re1 = (const unsigned long long*)smre;
        const unsigned long long* im1 = (const unsigned long long*)smim;
        for (int m = 0; m < MTOT; m++) {
            float2 y = g_Yc[m * NJK + jk];
            unsigned long long yb = pk2(y.x, y.x);
            float nyy = -y.y;
            unsigned long long ynb = pk2(nyy, nyy);
            ulonglong2 ra = re2[m * 3];
            ulonglong2 rb = re2[m * 3 + 1];
            unsigned long long rc = re1[m * 6 + 4];
            ulonglong2 ia = im2[m * 3];
            ulonglong2 ib = im2[m * 3 + 1];
            unsigned long long ic = im1[m * 6 + 4];
            fma2(acc2[0], ra.x, yb);  fma2(acc2[0], ia.x, ynb);
            fma2(acc2[1], ra.y, yb);  fma2(acc2[1], ia.y, ynb);
            fma2(acc2[2], rb.x, yb);  fma2(acc2[2], ib.x, ynb);
            fma2(acc2[3], rb.y, yb);  fma2(acc2[3], ib.y, ynb);
            fma2(acc2[4], rc,   yb);  fma2(acc2[4], ic,   ynb);
        }
        float acc[NREP];
#pragma unroll
        for (int p = 0; p < 5; p++) {
            float2 f = upk2(acc2[p]);
            acc[2 * p] = f.x;
            acc[2 * p + 1] = f.y;
        }
        int j = jk / 14, k = jk % 14;
        int kh = k >> 1;
#pragma unroll
        for (int r = 0; r < NREP; r++) {
            __half hv = __float2half(acc[r]);
            int rq = r * SIGQ_R_Q;
            sigH[4 * (rq + (j + 1) * 8 + kh) + (k & 1)] = hv;      // as top
            sigH[4 * (rq + j * 8 + kh) + 2 + (k & 1)] = hv;        // as bottom
            int b = SIGQ_XP_Q + rq;
            if (k & 1) {
                sigH[4 * (b + (j + 1) * 8 + kh) + 0] = hv;
                sigH[4 * (b + j * 8 + kh) + 2] = hv;
            } else if (k >= 2) {
                int hh = kh - 1;
                sigH[4 * (b + (j + 1) * 8 + hh) + 1] = hv;
                sigH[4 * (b + j * 8 + hh) + 3] = hv;
            }
        }
    }
    __syncthreads();

    // --- Phases C+D: two row-group passes (out rows 64g..64g+64) ---
    float* outn = out + (size_t)n * 16384;
    const float bias = c_bt[0];
#pragma unroll 1
    for (int g = 0; g < 2; g++) {
        // Phase C: proj rows [32g-1, 32g+33) -> transposed fp16 proj
        for (int task = tid; task < 33 * 34; task += BLOCK) {
            int w = task / 34;
            int srow = task - w * 34;
            int grow = 32 * g - 1 + srow;
            if ((unsigned)grow >= 64u) {
#pragma unroll
                for (int c = 0; c < NREP; c++)
                    projW[(c * 33 + w) * PROJ_SROW + srow] = 0u;
                continue;
            }
            int2 o2 = g_tqoT[w * 64 + grow];
            float4 wA = g_tqwT[(2 * w) * 64 + grow];
            float4 wB = g_tqwT[(2 * w + 1) * 64 + grow];
#pragma unroll
            for (int c = 0; c < NREP; c++) {
                int rq = c * SIGQ_R_Q;
                uint2 ra = sigQ2[o2.x + rq];
                uint2 rb = sigQ2[o2.y + rq];
                float2 at = __half22float2(*(__half2*)&ra.x);
                float2 ab = __half22float2(*(__half2*)&ra.y);
                float2 bt2 = __half22float2(*(__half2*)&rb.x);
                float2 bb = __half22float2(*(__half2*)&rb.y);
                float v0 = wA.x * at.x + wA.y * at.y + wA.z * ab.x + wA.w * ab.y;
                float v1 = wB.x * bt2.x + wB.y * bt2.y + wB.z * bb.x + wB.w * bb.y;
                __half2 pv = __floats2half2_rn(v0, v1);
                projW[(c * 33 + w) * PROJ_SROW + srow] = *(unsigned int*)&pv;
            }
        }
        __syncthreads();

        // Phase D: one 8x4 output tile per thread, packed dy-pair FFMA2
        {
            int b = tid >> 5;           // 0..7
            int tx = tid & 31;
            // acc2[p][dx]: pairs p -> (dy_lo, dy_lo+2), dy_lo = (p>>1)*4 + (p&1)
            unsigned long long acc2[4][4];
            unsigned long long bias2 = pk2(bias, bias);
#pragma unroll
            for (int p = 0; p < 4; p++)
#pragma unroll
                for (int dx = 0; dx < 4; dx++) acc2[p][dx] = bias2;

#pragma unroll
            for (int c = 0; c < NREP; c++) {
                float P[6][4];
#pragma unroll
                for (int wi = 0; wi < 2; wi++) {
                    int base = (c * 33 + tx + wi) * PROJ_SROW + 4 * b;
                    uint4 q  = *(const uint4*)&projW[base];
                    uint2 q2 = *(const uint2*)&projW[base + 4];
                    float2 f0 = __half22float2(*(__half2*)&q.x);
                    float2 f1 = __half22float2(*(__half2*)&q.y);
                    float2 f2 = __half22float2(*(__half2*)&q.z);
                    float2 f3 = __half22float2(*(__half2*)&q.w);
                    float2 f4 = __half22float2(*(__half2*)&q2.x);
                    float2 f5 = __half22float2(*(__half2*)&q2.y);
                    P[0][2 * wi] = f0.x; P[0][2 * wi + 1] = f0.y;
                    P[1][2 * wi] = f1.x; P[1][2 * wi + 1] = f1.y;
                    P[2][2 * wi] = f2.x; P[2][2 * wi + 1] = f2.y;
                    P[3][2 * wi] = f3.x; P[3][2 * wi + 1] = f3.y;
                    P[4][2 * wi] = f4.x; P[4][2 * wi + 1] = f4.y;
                    P[5][2 * wi] = f5.x; P[5][2 * wi + 1] = f5.y;
                }
#pragma unroll
                for (int p = 0; p < 4; p++) {
                    int py = p & 1;
                    int plb = (p >> 1) * 2;
                    int a0 = py ? plb + 2 : plb + 1;  // ry0 rows (a0, a0+1)
                    int a1 = py ? plb + 1 : plb;      // ry1 rows (a1, a1+1)
                    int kya = py ? 0 : 1;
                    int kyb = py ? 2 : 3;
#pragma unroll
                    for (int dx = 0; dx < 4; dx++) {
                        int ql = dx >> 1;
                        int px = dx & 1;
                        int rx0 = px ? ql + 2 : ql + 1;
                        int rx1 = px ? ql + 1 : ql;
                        int kxa = px ? 0 : 1;
                        int kxb = px ? 2 : 3;
                        float wa = c_wt[c * 16 + kya * 4 + kxa];
                        float wb = c_wt[c * 16 + kya * 4 + kxb];
                        float wc = c_wt[c * 16 + kyb * 4 + kxa];
                        float wd = c_wt[c * 16 + kyb * 4 + kxb];
                        fma2(acc2[p][dx], pk2(P[a0][rx0], P[a0 + 1][rx0]), pk2(wa, wa));
                        fma2(acc2[p][dx], pk2(P[a0][rx1], P[a0 + 1][rx1]), pk2(wb, wb));
                        fma2(acc2[p][dx], pk2(P[a1][rx0], P[a1 + 1][rx0]), pk2(wc, wc));
                        fma2(acc2[p][dx], pk2(P[a1][rx1], P[a1 + 1][rx1]), pk2(wd, wd));
                    }
                }
            }
            int orow0 = 64 * g + 8 * b;
#pragma unroll
            for (int p = 0; p < 4; p++) {
                int dy_lo = (p >> 1) * 4 + (p & 1);
                float2 e0 = upk2(acc2[p][0]);
                float2 e1 = upk2(acc2[p][1]);
                float2 e2 = upk2(acc2[p][2]);
                float2 e3 = upk2(acc2[p][3]);
                float4 vlo = make_float4(e0.x, e1.x, e2.x, e3.x);
                float4 vhi = make_float4(e0.y, e1.y, e2.y, e3.y);
                *reinterpret_cast<float4*>(outn + (size_t)(orow0 + dy_lo) * 128 + 4 * tx) = vlo;
                *reinterpret_cast<float4*>(outn + (size_t)(orow0 + dy_lo + 2) * 128 + 4 * tx) = vhi;
            }
        }
        if (g == 0) __syncthreads();   // protect proj before pass-1's C
    }
}

// ---------------------------------------------------------------------------
extern "C" void kernel_launch(void* const* d_in, const int* in_sizes, int n_in,
                              void* d_out, int out_size) {
    const float* angles   = (const float*)d_in[0];
    const float* spectrum = (const float*)d_in[1];
    const float* wt       = (const float*)d_in[2];
    const float* bt       = (const float*)d_in[3];
    float* out = (float*)d_out;

    cudaFuncSetAttribute(decoder_kernel,
                         cudaFuncAttributeMaxDynamicSharedMemorySize, SMEM_BYTES);

    cudaMemcpyToSymbolAsync(c_wt, wt, 160 * sizeof(float), 0,
                            cudaMemcpyDeviceToDevice);
    cudaMemcpyToSymbolAsync(c_bt, bt, sizeof(float), 0,
                            cudaMemcpyDeviceToDevice);

    // 64 blocks x 256 = 16384 threads: covers taps up to 8192+4224=12416.
    setup_kernel<<<64, 256>>>();
    decoder_kernel<<<NPOSE, BLOCK, SMEM_BYTES>>>(angles, spectrum, out);
}

// round 16
// speedup vs baseline: 2.5049x; 1.0316x over previous
#include <cuda_runtime.h>
#include <cuda_fp16.h>
#include <math.h>

// ---------------------------------------------------------------------------
// ProjectionDecoder: Wigner rotate -> S2 ifft -> grid_sample -> convtranspose
// angles (2048,3) f32; spectrum (49,10,2) f32; wt (10,1,4,4) f32; bt (1) f32
// out (2048,1,128,128) f32
//
// R14: LSU amortization. sigQ channel-innermost so phase-C gathers are
// 5x LDS.128 per tap (was 10x LDS.64); phase B handles 2 jk per thread
// (jk, jk+98) reusing each Srot load for both, Y packed float4.
// FFMA2 packed math retained in B and D.
// ---------------------------------------------------------------------------

#define NPOSE 2048
#define MTOT  49
#define NREP  10
#define NJK   196     // 14*14
#define NSLOT 4753    // sum (2l+1)^3, l=0..6
#define BLOCK 256

// sigQ (fp16, channel-inner): [group(240)][r(10)] quads, group = xp*120+yq*8+hh
//   quad halves = {s[yq-1][c0], s[yq-1][c0+1], s[yq][c0], s[yq][c0+1]}, c0=2*hh+xp
#define SIGQ_GRP    240
#define SIGQ_TOT_Q  2400
#define SIGQ_TOT_W  4800

// proj (per pass): [c(10)][word(33)][srow(36 padded, 34 used)] half2 words
#define PROJ_SROW   36
#define PROJ_C_W    (33 * PROJ_SROW)   // 1188

__device__ float2      g_tterm[NSLOT];     // {coef, bits(pc<<8|ps)}
__device__ float4      g_Yc4[MTOT * 98];   // {Yre(jk),Yim(jk),Yre(jk+98),Yim(jk+98)}
__device__ float4      g_tqwT[66 * 64];    // quad weights, [h][row]
__device__ int2        g_tqoT[33 * 64];    // quad base offsets*10 {oA,oB}, [w][row]

__constant__ float  c_wt[160];   // deconv weights (10 x 16)
__constant__ float  c_bt[1];     // bias
__constant__ double c_fact[13] = {
    1.0, 1.0, 2.0, 6.0, 24.0, 120.0, 720.0, 5040.0,
    40320.0, 362880.0, 3628800.0, 39916800.0, 479001600.0 };

__device__ __forceinline__ int slotbase(int l) { return l * l * (2 * l * l - 1); }
__device__ __forceinline__ int dloff(int l) { return l * (4 * l * l - 1) / 3; }

// --- packed fp32x2 helpers (FFMA2 path) ---
__device__ __forceinline__ unsigned long long pk2(float lo, float hi) {
    unsigned long long r;
    asm("mov.b64 %0, {%1, %2};" : "=l"(r) : "f"(lo), "f"(hi));
    return r;
}
__device__ __forceinline__ void fma2(unsigned long long& d,
                                     unsigned long long a,
                                     unsigned long long b) {
    asm("fma.rn.f32x2 %0, %1, %2, %0;" : "+l"(d) : "l"(a), "l"(b));
}
__device__ __forceinline__ float2 upk2(unsigned long long v) {
    float lo, hi;
    asm("mov.b64 {%0, %1}, %2;" : "=f"(lo), "=f"(hi) : "l"(v));
    return make_float2(lo, hi);
}

#define PI_F 3.14159265358979323846f

// ---------------------------------------------------------------------------
// Setup kernel: input-independent tables.
// ---------------------------------------------------------------------------
__global__ void setup_kernel() {
    int g = blockIdx.x * blockDim.x + threadIdx.x;

    if (g < NSLOT) {
        int l = (g >= 1) + (g >= 28) + (g >= 153) + (g >= 496) + (g >= 1225) + (g >= 2556);
        int n1 = 2 * l + 1;
        int rem = g - slotbase(l);
        int i = rem / (n1 * n1);
        int j = (rem / n1) % n1;
        int k = rem % n1;
        int mp = i - l, m = j - l;
        int kmin = max(0, m - mp);
        int kmax = min(l + m, l - mp);
        float coef = 0.0f;
        int pc = 0, ps = 0;
        if (k >= kmin && k <= kmax) {
            double pref = sqrt(c_fact[l + mp] * c_fact[l - mp] * c_fact[l + m] * c_fact[l - m]);
            double c = pref / (c_fact[l + m - k] * c_fact[k] * c_fact[l - mp - k] * c_fact[mp - m + k]);
            if ((mp - m + k) & 1) c = -c;
            coef = (float)c;
            pc = 2 * l + m - mp - 2 * k;
            ps = mp - m + 2 * k;
        }
        g_tterm[g] = make_float2(coef, __int_as_float((pc << 8) | ps));
    } else if (g >= 5120 && g < 5120 + NJK) {
        // Spherical harmonic table Y (49, 14, 14), packed float4 (jk, jk+98)
        int jk = g - 5120;
        int j = jk / 14, k = jk % 14;
        int jkh = (jk < 98) ? jk : jk - 98;
        int comp = (jk < 98) ? 0 : 2;
        float* Yf = (float*)g_Yc4;
        float beta = PI_F * (2.0f * j + 1.0f) / 28.0f;
        float x, sx;
        sincosf(beta, &sx, &x);
        float P[7][7];
#pragma unroll
        for (int a = 0; a < 7; a++)
#pragma unroll
            for (int b = 0; b < 7; b++) P[a][b] = 0.0f;
        P[0][0] = 1.0f;
        for (int m = 1; m <= 6; m++) P[m][m] = -(2.0f * m - 1.0f) * sx * P[m - 1][m - 1];
        for (int m = 0; m <= 6; m++) {
            if (m + 1 <= 6) P[m + 1][m] = (2.0f * m + 1.0f) * x * P[m][m];
            for (int l = m + 2; l <= 6; l++)
                P[l][m] = ((2.0f * l - 1.0f) * x * P[l - 1][m] - (l + m - 1.0f) * P[l - 2][m]) / (float)(l - m);
        }
        float alk = 2.0f * PI_F * (float)k / 14.0f;
        for (int l = 0; l <= 6; l++) {
            for (int m = 0; m <= l; m++) {
                float Nn = sqrtf((2.0f * l + 1.0f) / (4.0f * PI_F)
                                 * (float)(c_fact[l - m] / c_fact[l + m]));
                float pr = Nn * P[l][m];
                float sm_, cm_;
                sincosf((float)m * alk, &sm_, &cm_);
                float yre = pr * cm_;
                float yim = pr * sm_;
                int b0 = ((l * l + l + m) * 98 + jkh) * 4 + comp;
                Yf[b0] = yre;
                Yf[b0 + 1] = yim;
                if (m > 0) {
                    float sgn = (m & 1) ? -1.0f : 1.0f;
                    int b1 = ((l * l + l - m) * 98 + jkh) * 4 + comp;
                    Yf[b1] = sgn * yre;
                    Yf[b1 + 1] = -sgn * yim;
                }
            }
        }
    } else if (g >= 8192 && g < 8192 + 64 * 66) {
        // Quad tap entry for (proj row, stored h), TRANSPOSED tables.
        int idx = g - 8192;
        int row = idx / 66;
        int h = idx % 66;
        int col = h - 1;
        float4 w4 = make_float4(0.f, 0.f, 0.f, 0.f);
        int off = 0;
        if (col >= 0 && col < 64) {
            float step = 1.6f / 63.0f;
            float yv = -0.8f + row * step;
            float xv = -0.8f + col * step;
            float rho = sqrtf(xv * xv + yv * yv);
            float th = asinf(fminf(rho, 1.0f));
            float ph = atan2f(yv, xv);
            float gx = ph / PI_F;
            float gy = 2.0f * th / PI_F - 1.0f;
            float gpx = (gx + 1.0f) * 7.0f - 0.5f;
            float gpy = (gy + 1.0f) * 7.0f - 0.5f;
            float x0f = floorf(gpx), y0f = floorf(gpy);
            int x0 = (int)x0f, y0 = (int)y0f;   // in [-1,13]
            float fx = gpx - x0f, fy = gpy - y0f;
            float wx0 = 1.0f - fx, wx1 = fx;
            float wy0 = 1.0f - fy, wy1 = fy;
            float vy0 = (y0 >= 0) ? 1.0f : 0.0f;
            float vy1 = (y0 + 1 <= 13) ? 1.0f : 0.0f;
            int xp, hh;
            if (x0 >= 0) {
                float vx1 = (x0 + 1 <= 13) ? 1.0f : 0.0f;
                xp = x0 & 1;
                hh = x0 >> 1;
                w4 = make_float4(wx0 * wy0 * vy0, wx1 * wy0 * vx1 * vy0,
                                 wx0 * wy1 * vy1, wx1 * wy1 * vx1 * vy1);
            } else {  // x0 == -1
                xp = 0; hh = 0;
                w4 = make_float4(wx1 * wy0 * vy0, 0.0f,
                                 wx1 * wy1 * vy1, 0.0f);
            }
            off = (xp * 120 + (y0 + 1) * 8 + hh) * NREP;   // channel-inner base
        }
        g_tqwT[h * 64 + row] = w4;
        ((int*)g_tqoT)[((h >> 1) * 64 + row) * 2 + (h & 1)] = off;
    }
}

// ---------------------------------------------------------------------------
// Main fused kernel: one block (256 threads) per pose n, 3 blocks/SM.
// smem word layout (4B words):
//   dS [0,455)  cpow [455,468)  spow [468,481)
//   cA [481,488) sA [488,495) cG [495,502) sG [502,509)
//   SrotRe [512,1100)   re plane, 49 rows x 12 (10 used)
//   SrotIm [1100,1688)  im plane
//   sigQ   [1688,6488)  fp16 quads, channel-inner, uint2 each
//   proj   [6488,18368) fp16 projection [c][word][srow36]
#define SROT_RE   512
#define SROT_IM   1100
#define SIGQ_OFF  1688
#define PROJ_OFF  6488
#define SMEM_WORDS 18368
#define SMEM_BYTES (SMEM_WORDS * 4)

__global__ void __launch_bounds__(BLOCK, 3)
decoder_kernel(const float* __restrict__ angles,
               const float* __restrict__ spectrum,
               float* __restrict__ out) {
    extern __shared__ float sm[];
    float*  dS   = sm;
    float*  cpow = sm + 455;
    float*  spow = sm + 468;
    float*  cA   = sm + 481;
    float*  sA   = sm + 488;
    float*  cG   = sm + 495;
    float*  sG   = sm + 502;
    float*  smre = sm + SROT_RE;
    float*  smim = sm + SROT_IM;
    unsigned int* sigQW = (unsigned int*)(sm + SIGQ_OFF);
    __half* sigH = (__half*)(sm + SIGQ_OFF);
    const uint2* sigQ2 = (const uint2*)(sm + SIGQ_OFF);
    unsigned int* projW = (unsigned int*)(sm + PROJ_OFF);

    const int n = blockIdx.x;
    const int tid = threadIdx.x;

    const float alpha = angles[3 * n + 0];
    const float beta  = angles[3 * n + 1];
    const float gamma = angles[3 * n + 2];

    // --- Phase A0: trig tables, zero sig quads ---
    if (tid < 7) {
        float s, c;
        sincosf((float)tid * alpha, &s, &c);
        cA[tid] = c; sA[tid] = s;
    } else if (tid < 14) {
        int m = tid - 7;
        float s, c;
        sincosf((float)m * gamma, &s, &c);
        cG[m] = c; sG[m] = s;
    } else if (tid == 14) {
        float sb, cb;
        sincosf(0.5f * beta, &sb, &cb);
        float cp = 1.0f, spw = 1.0f;
#pragma unroll
        for (int e = 0; e < 13; e++) {
            cpow[e] = cp; spow[e] = spw;
            cp *= cb; spw *= sb;
        }
    }
    for (int i = tid; i < SIGQ_TOT_W; i += BLOCK) sigQW[i] = 0u;
    __syncthreads();

    // --- Phase A1: Wigner small-d matrices (packed term table) ---
    for (int t = tid; t < 455; t += BLOCK) {
        int l = (t >= 1) + (t >= 10) + (t >= 35) + (t >= 84) + (t >= 165) + (t >= 286);
        int n1 = 2 * l + 1;
        int loc = t - dloff(l);
        int base = slotbase(l) + loc * n1;
        float sum = 0.0f;
        for (int k = 0; k < n1; k++) {
            float2 tm = g_tterm[base + k];
            int bits = __float_as_int(tm.y);
            sum += tm.x * cpow[bits >> 8] * spow[bits & 255];
        }
        dS[t] = sum;
    }
    __syncthreads();

    // --- Phase A2: complex Wigner-D rotate -> re/im planes ---
    if (tid < 2 * MTOT) {
        int row = tid >> 1;
        int rbase = (tid & 1) * 5;
        int l = (row >= 1) + (row >= 4) + (row >= 9) + (row >= 16) + (row >= 25) + (row >= 36);
        int i = row - l * l;
        int mp = i - l;
        int n1 = 2 * l + 1;
        float camp = cA[mp < 0 ? -mp : mp];
        float samp = mp < 0 ? -sA[-mp] : sA[mp];
        float are[5], aim[5];
#pragma unroll
        for (int r = 0; r < 5; r++) { are[r] = 0.0f; aim[r] = 0.0f; }
        const float* drow = dS + dloff(l) + i * n1;
        for (int j = 0; j < n1; j++) {
            int m = j - l;
            float cg = cG[m < 0 ? -m : m];
            float sg = m < 0 ? -sG[-m] : sG[m];
            float cosang = camp * cg - samp * sg;
            float sinang = samp * cg + camp * sg;
            float dd = drow[j];
            float Dre = dd * cosang;
            float Dim = -dd * sinang;
            const float* sp2 = spectrum + (l * l + j) * 2 * NREP + 2 * rbase;
#pragma unroll
            for (int r = 0; r < 5; r++) {
                float sre = sp2[2 * r];
                float sim = sp2[2 * r + 1];
                are[r] += Dre * sre - Dim * sim;
                aim[r] += Dre * sim + Dim * sre;
            }
        }
#pragma unroll
        for (int r = 0; r < 5; r++) {
            smre[row * 12 + rbase + r] = are[r];
            smim[row * 12 + rbase + r] = aim[r];
        }
    }
    __syncthreads();

    // --- Phase B: S2 inverse (FFMA2, 2 jk per thread) -> fp16 quads ---
    if (tid < 98) {
        unsigned long long acc2a[5], acc2b[5];   // jk0 = tid, jk1 = tid + 98
        unsigned long long z = pk2(0.0f, 0.0f);
#pragma unroll
        for (int p = 0; p < 5; p++) { acc2a[p] = z; acc2b[p] = z; }
        const ulonglong2* re2 = (const ulonglong2*)smre;
        const ulonglong2* im2 = (const ulonglong2*)smim;
        const unsigned long long* re1 = (const unsigned long long*)smre;
        const unsigned long long* im1 = (const unsigned long long*)smim;
        for (int m = 0; m < MTOT; m++) {
            float4 y = g_Yc4[m * 98 + tid];
            unsigned long long yb0 = pk2(y.x, y.x);
            unsigned long long yn0 = pk2(-y.y, -y.y);
            unsigned long long yb1 = pk2(y.z, y.z);
            unsigned long long yn1 = pk2(-y.w, -y.w);
            ulonglong2 ra = re2[m * 3];
            ulonglong2 rb = re2[m * 3 + 1];
            unsigned long long rc = re1[m * 6 + 4];
            ulonglong2 ia = im2[m * 3];
            ulonglong2 ib = im2[m * 3 + 1];
            unsigned long long ic = im1[m * 6 + 4];
            fma2(acc2a[0], ra.x, yb0);  fma2(acc2a[0], ia.x, yn0);
            fma2(acc2a[1], ra.y, yb0);  fma2(acc2a[1], ia.y, yn0);
            fma2(acc2a[2], rb.x, yb0);  fma2(acc2a[2], ib.x, yn0);
            fma2(acc2a[3], rb.y, yb0);  fma2(acc2a[3], ib.y, yn0);
            fma2(acc2a[4], rc,   yb0);  fma2(acc2a[4], ic,   yn0);
            fma2(acc2b[0], ra.x, yb1);  fma2(acc2b[0], ia.x, yn1);
            fma2(acc2b[1], ra.y, yb1);  fma2(acc2b[1], ia.y, yn1);
            fma2(acc2b[2], rb.x, yb1);  fma2(acc2b[2], ib.x, yn1);
            fma2(acc2b[3], rb.y, yb1);  fma2(acc2b[3], ib.y, yn1);
            fma2(acc2b[4], rc,   yb1);  fma2(acc2b[4], ic,   yn1);
        }
#pragma unroll
        for (int half = 0; half < 2; half++) {
            int jk = tid + half * 98;
            int j = jk / 14, k = jk % 14;
            int kh = k >> 1;
            float acc[NREP];
#pragma unroll
            for (int p = 0; p < 5; p++) {
                float2 f = upk2(half ? acc2b[p] : acc2a[p]);
                acc[2 * p] = f.x;
                acc[2 * p + 1] = f.y;
            }
#pragma unroll
            for (int r = 0; r < NREP; r++) {
                __half hv = __float2half(acc[r]);
                // channel-inner: half index = (group*10 + r)*4 + sub
                int gtop = (j + 1) * 8 + kh;      // xp0 groups
                int gbot = j * 8 + kh;
                sigH[4 * (gtop * NREP + r) + (k & 1)] = hv;
                sigH[4 * (gbot * NREP + r) + 2 + (k & 1)] = hv;
                if (k & 1) {
                    sigH[4 * ((120 + gtop) * NREP + r) + 0] = hv;
                    sigH[4 * ((120 + gbot) * NREP + r) + 2] = hv;
                } else if (k >= 2) {
                    int gt1 = (j + 1) * 8 + kh - 1;
                    int gb1 = j * 8 + kh - 1;
                    sigH[4 * ((120 + gt1) * NREP + r) + 1] = hv;
                    sigH[4 * ((120 + gb1) * NREP + r) + 3] = hv;
                }
            }
        }
    }
    __syncthreads();

    // --- Phases C+D: two row-group passes (out rows 64g..64g+64) ---
    float* outn = out + (size_t)n * 16384;
    const float bias = c_bt[0];
#pragma unroll 1
    for (int g = 0; g < 2; g++) {
        // Phase C: proj rows [32g-1, 32g+33) -> transposed fp16 proj
        for (int task = tid; task < 33 * 34; task += BLOCK) {
            int w = task / 34;
            int srow = task - w * 34;
            int grow = 32 * g - 1 + srow;
            if ((unsigned)grow >= 64u) {
#pragma unroll
                for (int c = 0; c < NREP; c++)
                    projW[(c * 33 + w) * PROJ_SROW + srow] = 0u;
                continue;
            }
            int2 o2 = g_tqoT[w * 64 + grow];
            float4 wA = g_tqwT[(2 * w) * 64 + grow];
            float4 wB = g_tqwT[(2 * w + 1) * 64 + grow];
            // channel-inner gathers: 10 quads each = 5 LDS.128
            uint4 A[5], B[5];
            const uint4* qa = (const uint4*)(sigQ2 + o2.x);
            const uint4* qb = (const uint4*)(sigQ2 + o2.y);
#pragma unroll
            for (int q = 0; q < 5; q++) { A[q] = qa[q]; B[q] = qb[q]; }
#pragma unroll
            for (int c = 0; c < NREP; c++) {
                unsigned int at_w = (c & 1) ? A[c >> 1].z : A[c >> 1].x;
                unsigned int ab_w = (c & 1) ? A[c >> 1].w : A[c >> 1].y;
                unsigned int bt_w = (c & 1) ? B[c >> 1].z : B[c >> 1].x;
                unsigned int bb_w = (c & 1) ? B[c >> 1].w : B[c >> 1].y;
                float2 at = __half22float2(*(__half2*)&at_w);
                float2 ab = __half22float2(*(__half2*)&ab_w);
                float2 bt2 = __half22float2(*(__half2*)&bt_w);
                float2 bb = __half22float2(*(__half2*)&bb_w);
                float v0 = wA.x * at.x + wA.y * at.y + wA.z * ab.x + wA.w * ab.y;
                float v1 = wB.x * bt2.x + wB.y * bt2.y + wB.z * bb.x + wB.w * bb.y;
                __half2 pv = __floats2half2_rn(v0, v1);
                projW[(c * 33 + w) * PROJ_SROW + srow] = *(unsigned int*)&pv;
            }
        }
        __syncthreads();

        // Phase D: one 8x4 output tile per thread, packed dy-pair FFMA2
        {
            int b = tid >> 5;           // 0..7
            int tx = tid & 31;
            unsigned long long acc2[4][4];
            unsigned long long bias2 = pk2(bias, bias);
#pragma unroll
            for (int p = 0; p < 4; p++)
#pragma unroll
                for (int dx = 0; dx < 4; dx++) acc2[p][dx] = bias2;

#pragma unroll
            for (int c = 0; c < NREP; c++) {
                float P[6][4];
#pragma unroll
                for (int wi = 0; wi < 2; wi++) {
                    int base = (c * 33 + tx + wi) * PROJ_SROW + 4 * b;
                    uint4 q  = *(const uint4*)&projW[base];
                    uint2 q2 = *(const uint2*)&projW[base + 4];
                    float2 f0 = __half22float2(*(__half2*)&q.x);
                    float2 f1 = __half22float2(*(__half2*)&q.y);
                    float2 f2 = __half22float2(*(__half2*)&q.z);
                    float2 f3 = __half22float2(*(__half2*)&q.w);
                    float2 f4 = __half22float2(*(__half2*)&q2.x);
                    float2 f5 = __half22float2(*(__half2*)&q2.y);
                    P[0][2 * wi] = f0.x; P[0][2 * wi + 1] = f0.y;
                    P[1][2 * wi] = f1.x; P[1][2 * wi + 1] = f1.y;
                    P[2][2 * wi] = f2.x; P[2][2 * wi + 1] = f2.y;
                    P[3][2 * wi] = f3.x; P[3][2 * wi + 1] = f3.y;
                    P[4][2 * wi] = f4.x; P[4][2 * wi + 1] = f4.y;
                    P[5][2 * wi] = f5.x; P[5][2 * wi + 1] = f5.y;
                }
#pragma unroll
                for (int p = 0; p < 4; p++) {
                    int py = p & 1;
                    int plb = (p >> 1) * 2;
                    int a0 = py ? plb + 2 : plb + 1;
                    int a1 = py ? plb + 1 : plb;
                    int kya = py ? 0 : 1;
                    int kyb = py ? 2 : 3;
#pragma unroll
                    for (int dx = 0; dx < 4; dx++) {
                        int ql = dx >> 1;
                        int px = dx & 1;
                        int rx0 = px ? ql + 2 : ql + 1;
                        int rx1 = px ? ql + 1 : ql;
                        int kxa = px ? 0 : 1;
                        int kxb = px ? 2 : 3;
                        float wa = c_wt[c * 16 + kya * 4 + kxa];
                        float wb = c_wt[c * 16 + kya * 4 + kxb];
                        float wc = c_wt[c * 16 + kyb * 4 + kxa];
                        float wd = c_wt[c * 16 + kyb * 4 + kxb];
                        fma2(acc2[p][dx], pk2(P[a0][rx0], P[a0 + 1][rx0]), pk2(wa, wa));
                        fma2(acc2[p][dx], pk2(P[a0][rx1], P[a0 + 1][rx1]), pk2(wb, wb));
                        fma2(acc2[p][dx], pk2(P[a1][rx0], P[a1 + 1][rx0]), pk2(wc, wc));
                        fma2(acc2[p][dx], pk2(P[a1][rx1], P[a1 + 1][rx1]), pk2(wd, wd));
                    }
                }
            }
            int orow0 = 64 * g + 8 * b;
#pragma unroll
            for (int p = 0; p < 4; p++) {
                int dy_lo = (p >> 1) * 4 + (p & 1);
                float2 e0 = upk2(acc2[p][0]);
                float2 e1 = upk2(acc2[p][1]);
                float2 e2 = upk2(acc2[p][2]);
                float2 e3 = upk2(acc2[p][3]);
                float4 vlo = make_float4(e0.x, e1.x, e2.x, e3.x);
                float4 vhi = make_float4(e0.y, e1.y, e2.y, e3.y);
                *reinterpret_cast<float4*>(outn + (size_t)(orow0 + dy_lo) * 128 + 4 * tx) = vlo;
                *reinterpret_cast<float4*>(outn + (size_t)(orow0 + dy_lo + 2) * 128 + 4 * tx) = vhi;
            }
        }
        if (g == 0) __syncthreads();   // protect proj before pass-1's C
    }
}

// ---------------------------------------------------------------------------
extern "C" void kernel_launch(void* const* d_in, const int* in_sizes, int n_in,
                              void* d_out, int out_size) {
    const float* angles   = (const float*)d_in[0];
    const float* spectrum = (const float*)d_in[1];
    const float* wt       = (const float*)d_in[2];
    const float* bt       = (const float*)d_in[3];
    float* out = (float*)d_out;

    cudaFuncSetAttribute(decoder_kernel,
                         cudaFuncAttributeMaxDynamicSharedMemorySize, SMEM_BYTES);

    cudaMemcpyToSymbolAsync(c_wt, wt, 160 * sizeof(float), 0,
                            cudaMemcpyDeviceToDevice);
    cudaMemcpyToSymbolAsync(c_bt, bt, sizeof(float), 0,
                            cudaMemcpyDeviceToDevice);

    // 64 blocks x 256 = 16384 threads: covers taps up to 8192+4224=12416.
    setup_kernel<<<64, 256>>>();
    decoder_kernel<<<NPOSE, BLOCK, SMEM_BYTES>>>(angles, spectrum, out);
}